// round 1
// baseline (speedup 1.0000x reference)
#include <cuda_runtime.h>

// ---------------- problem constants ----------------
static constexpr int Bsz   = 16384;
static constexpr int Dm    = 256;
static constexpr int Dh    = 512;
static constexpr int NNUM  = 32;
static constexpr int NCAT  = 16;
static constexpr int KFIRST = NNUM + NCAT * Dm;   // 32 + 4096 = 4128

// ---------------- scratch (static device globals; no runtime alloc) ----------
__device__ float g_h  [Bsz * Dm];    // residual stream
__device__ float g_ln [Bsz * Dm];    // layernorm output
__device__ float g_t  [Bsz * Dh];    // hidden activations
__device__ float g_Anum[NNUM * Dm];  // folded numerical weights (32x256)
__device__ float g_c  [Dm];          // folded first-layer bias

// ---------------- f32x2 packed math helpers (sm_103a FFMA2) ------------------
__device__ __forceinline__ unsigned long long pk2(float lo, float hi) {
    unsigned long long r;
    asm("mov.b64 %0, {%1, %2};" : "=l"(r) : "f"(lo), "f"(hi));
    return r;
}
__device__ __forceinline__ void fma2(unsigned long long& d, unsigned long long a, unsigned long long b) {
    asm("fma.rn.f32x2 %0, %1, %2, %0;" : "+l"(d) : "l"(a), "l"(b));
}
__device__ __forceinline__ float2 up2(unsigned long long v) {
    float lo, hi;
    asm("mov.b64 {%0, %1}, %2;" : "=f"(lo), "=f"(hi) : "l"(v));
    return make_float2(lo, hi);
}

// ---------------- prep: fold w_num/b_num through W_first ---------------------
// A_num[f][j] = sum_d w_num[f,d] * W_first[f*256+d, j]
__global__ void prep_anum(const float* __restrict__ w_num, const float* __restrict__ W_first) {
    int f = blockIdx.x;          // 0..31
    int j = threadIdx.x;         // 0..255
    const float* Wf = W_first + (size_t)f * 256 * 256 + j;
    const float* wn = w_num + f * 256;
    float acc = 0.f;
    for (int d = 0; d < 256; d++) acc = fmaf(wn[d], Wf[(size_t)d * 256], acc);
    g_Anum[f * 256 + j] = acc;
}

// c[j] = b_first[j] + sum_{k<8192} b_num[k] * W_first[k, j]
__global__ void prep_c(const float* __restrict__ b_num, const float* __restrict__ W_first,
                       const float* __restrict__ b_first) {
    int j = threadIdx.x;
    float acc = b_first[j];
    for (int k = 0; k < NNUM * 256; k++)
        acc = fmaf(b_num[k], W_first[(size_t)k * 256 + j], acc);
    g_c[j] = acc;
}

// ---------------- shared 128x128 tile mainloop --------------------------------
__device__ __forceinline__ void mm_tile(float (&As)[16][132], float (&Bs)[16][128],
                                        int row0, int col0, unsigned long long (&acc)[4][8]) {
#pragma unroll
    for (int kk = 0; kk < 16; kk++) {
        float4 a0 = *(float4*)&As[kk][row0];
        float4 a1 = *(float4*)&As[kk][row0 + 4];
        float4 b0 = *(float4*)&Bs[kk][col0];
        float4 b1 = *(float4*)&Bs[kk][col0 + 4];
        unsigned long long ap[4] = { pk2(a0.x, a0.y), pk2(a0.z, a0.w),
                                     pk2(a1.x, a1.y), pk2(a1.z, a1.w) };
        float bv[8] = { b0.x, b0.y, b0.z, b0.w, b1.x, b1.y, b1.z, b1.w };
#pragma unroll
        for (int j = 0; j < 8; j++) {
            unsigned long long bd = pk2(bv[j], bv[j]);
#pragma unroll
            for (int i = 0; i < 4; i++) fma2(acc[i][j], ap[i], bd);
        }
    }
}

template <int RELU, int RES>
__device__ __forceinline__ void epilogue(unsigned long long (&acc)[4][8],
                                         const float* __restrict__ bias,
                                         const float* __restrict__ res,
                                         float* __restrict__ C, int N,
                                         int bm, int bn, int row0, int col0) {
    float bcol[8];
#pragma unroll
    for (int j = 0; j < 8; j++) bcol[j] = bias[bn + col0 + j];
#pragma unroll
    for (int i = 0; i < 4; i++) {
        int r0 = bm + row0 + 2 * i;
        float o0[8], o1[8];
#pragma unroll
        for (int j = 0; j < 8; j++) {
            float2 v = up2(acc[i][j]);
            o0[j] = v.x + bcol[j];
            o1[j] = v.y + bcol[j];
        }
        if (RELU) {
#pragma unroll
            for (int j = 0; j < 8; j++) { o0[j] = fmaxf(o0[j], 0.f); o1[j] = fmaxf(o1[j], 0.f); }
        }
        if (RES) {
            const float* rp0 = res + (size_t)r0 * N + bn + col0;
            const float* rp1 = rp0 + N;
#pragma unroll
            for (int j = 0; j < 8; j++) { o0[j] += rp0[j]; o1[j] += rp1[j]; }
        }
        float* cp0 = C + (size_t)r0 * N + bn + col0;
        float* cp1 = cp0 + N;
        *(float4*)(cp0)     = make_float4(o0[0], o0[1], o0[2], o0[3]);
        *(float4*)(cp0 + 4) = make_float4(o0[4], o0[5], o0[6], o0[7]);
        *(float4*)(cp1)     = make_float4(o1[0], o1[1], o1[2], o1[3]);
        *(float4*)(cp1 + 4) = make_float4(o1[4], o1[5], o1[6], o1[7]);
    }
}

// ---------------- MLP GEMMs ----------------------------------------------------
// MODE 1: g_t = relu(g_ln @ W1 + b1)           K=256, N=512
// MODE 2: g_h = g_h + (g_t @ W2 + b2)          K=512, N=256
template <int MODE>
__global__ __launch_bounds__(256) void gemm_mlp(const float* __restrict__ Bm,
                                                const float* __restrict__ bias) {
    constexpr int K = (MODE == 1) ? Dm : Dh;
    constexpr int N = (MODE == 1) ? Dh : Dm;
    const float* A = (MODE == 1) ? g_ln : g_t;
    float*       C = (MODE == 1) ? g_t  : g_h;

    __shared__ __align__(16) float As[16][132];
    __shared__ __align__(16) float Bs[16][128];

    int tid  = threadIdx.x;
    int bm   = blockIdx.x * 128;
    int bn   = blockIdx.y * 128;
    int row0 = (tid >> 4) << 3;
    int col0 = (tid & 15) << 3;
    int am   = tid >> 1;
    int ak   = (tid & 1) << 3;

    unsigned long long acc[4][8] = {};
    const float* Arow = A + (size_t)(bm + am) * K + ak;

    for (int k0 = 0; k0 < K; k0 += 16) {
        float4 a0 = *(const float4*)(Arow + k0);
        float4 a1 = *(const float4*)(Arow + k0 + 4);
        As[ak + 0][am] = a0.x; As[ak + 1][am] = a0.y;
        As[ak + 2][am] = a0.z; As[ak + 3][am] = a0.w;
        As[ak + 4][am] = a1.x; As[ak + 5][am] = a1.y;
        As[ak + 6][am] = a1.z; As[ak + 7][am] = a1.w;
#pragma unroll
        for (int i = 0; i < 2; i++) {
            int idx = tid + i * 256;
            int bk = idx >> 5, bn4 = (idx & 31) << 2;
            *(float4*)&Bs[bk][bn4] = *(const float4*)&Bm[(size_t)(k0 + bk) * N + bn + bn4];
        }
        __syncthreads();
        mm_tile(As, Bs, row0, col0, acc);
        __syncthreads();
    }
    epilogue<(MODE == 1) ? 1 : 0, (MODE == 2) ? 1 : 0>(acc, bias, g_h, C, N, bm, bn, row0, col0);
}

// ---------------- first layer: gathered GEMM, K = 32 (num) + 4096 (cat) -------
__global__ __launch_bounds__(256) void gemm_first(const float* __restrict__ x_num,
                                                  const int*   __restrict__ xidx,
                                                  const float* __restrict__ cat_embed,
                                                  const float* __restrict__ W_first) {
    __shared__ __align__(16) float As[16][132];
    __shared__ __align__(16) float Bs[16][128];

    int tid  = threadIdx.x;
    int bm   = blockIdx.x * 128;
    int bn   = blockIdx.y * 128;
    int row0 = (tid >> 4) << 3;
    int col0 = (tid & 15) << 3;
    int am   = tid >> 1;
    int ak   = (tid & 1) << 3;
    int m    = bm + am;

    unsigned long long acc[4][8] = {};

    for (int k0 = 0; k0 < KFIRST; k0 += 16) {
        float4 a0, a1;
        const float* Bsrc;
        if (k0 < NNUM) {
            const float* xp = x_num + (size_t)m * NNUM + k0 + ak;
            a0 = *(const float4*)xp;
            a1 = *(const float4*)(xp + 4);
            Bsrc = g_Anum + k0 * 256;
        } else {
            int kc = k0 - NNUM + ak;              // 0..4095
            int f = kc >> 8, d = kc & 255;
            const float* ep = cat_embed + (size_t)xidx[m * NCAT + f] * 256 + d;
            a0 = *(const float4*)ep;
            a1 = *(const float4*)(ep + 4);
            Bsrc = W_first + (size_t)(NNUM * 256 + k0 - NNUM) * 256;
        }
        As[ak + 0][am] = a0.x; As[ak + 1][am] = a0.y;
        As[ak + 2][am] = a0.z; As[ak + 3][am] = a0.w;
        As[ak + 4][am] = a1.x; As[ak + 5][am] = a1.y;
        As[ak + 6][am] = a1.z; As[ak + 7][am] = a1.w;
#pragma unroll
        for (int i = 0; i < 2; i++) {
            int idx = tid + i * 256;
            int bk = idx >> 5, bn4 = (idx & 31) << 2;
            *(float4*)&Bs[bk][bn4] = *(const float4*)&Bsrc[(size_t)bk * 256 + bn + bn4];
        }
        __syncthreads();
        mm_tile(As, Bs, row0, col0, acc);
        __syncthreads();
    }
    epilogue<0, 0>(acc, g_c, g_h, g_h, Dm, bm, bn, row0, col0);
}

// ---------------- layernorm + head --------------------------------------------
__device__ __forceinline__ float blockSum(float v) {
    __shared__ float sm[8];
    int lane = threadIdx.x & 31, w = threadIdx.x >> 5;
#pragma unroll
    for (int o = 16; o; o >>= 1) v += __shfl_xor_sync(0xffffffffu, v, o);
    if (lane == 0) sm[w] = v;
    __syncthreads();
    if (w == 0) {
        float s = (lane < 8) ? sm[lane] : 0.f;
#pragma unroll
        for (int o = 4; o; o >>= 1) s += __shfl_xor_sync(0xffffffffu, s, o);
        if (lane == 0) sm[0] = s;
    }
    __syncthreads();
    float r = sm[0];
    __syncthreads();
    return r;
}

__global__ void ln_kernel(const float* __restrict__ g, const float* __restrict__ b) {
    int row = blockIdx.x, t = threadIdx.x;
    float v = g_h[(size_t)row * Dm + t];
    float mu = blockSum(v) * (1.f / 256.f);
    float d = v - mu;
    float var = blockSum(d * d) * (1.f / 256.f);
    g_ln[(size_t)row * Dm + t] = d * rsqrtf(var + 1e-5f) * g[t] + b[t];
}

__global__ void head_kernel(const float* __restrict__ g, const float* __restrict__ b,
                            const float* __restrict__ Wh, const float* __restrict__ bh,
                            float* __restrict__ out) {
    int row = blockIdx.x, t = threadIdx.x;
    float v = g_h[(size_t)row * Dm + t];
    float mu = blockSum(v) * (1.f / 256.f);
    float d = v - mu;
    float var = blockSum(d * d) * (1.f / 256.f);
    float y = d * rsqrtf(var + 1e-5f) * g[t] + b[t];
    float s0 = blockSum(y * Wh[t * 2 + 0]);
    float s1 = blockSum(y * Wh[t * 2 + 1]);
    if (t == 0) {
        out[row * 2 + 0] = s0 + bh[0];
        out[row * 2 + 1] = s1 + bh[1];
    }
}

// ---------------- launch --------------------------------------------------------
extern "C" void kernel_launch(void* const* d_in, const int* in_sizes, int n_in,
                              void* d_out, int out_size) {
    const float* x_num    = (const float*)d_in[0];
    const int*   xidx     = (const int*)  d_in[1];
    const float* w_num    = (const float*)d_in[2];
    const float* b_num    = (const float*)d_in[3];
    const float* cat_emb  = (const float*)d_in[4];
    const float* W_first  = (const float*)d_in[5];
    const float* b_first  = (const float*)d_in[6];
    const float* ln_g     = (const float*)d_in[7];
    const float* ln_b     = (const float*)d_in[8];
    const float* W1s      = (const float*)d_in[9];
    const float* b1s      = (const float*)d_in[10];
    const float* W2s      = (const float*)d_in[11];
    const float* b2s      = (const float*)d_in[12];
    const float* g_f      = (const float*)d_in[13];
    const float* beta_f   = (const float*)d_in[14];
    const float* W_head   = (const float*)d_in[15];
    const float* b_head   = (const float*)d_in[16];

    prep_anum<<<NNUM, 256>>>(w_num, W_first);
    prep_c<<<1, 256>>>(b_num, W_first, b_first);

    gemm_first<<<dim3(Bsz / 128, Dm / 128), 256>>>(x_num, xidx, cat_emb, W_first);

    for (int l = 0; l < 8; l++) {
        ln_kernel<<<Bsz, 256>>>(ln_g + l * Dm, ln_b + l * Dm);
        gemm_mlp<1><<<dim3(Bsz / 128, Dh / 128), 256>>>(W1s + (size_t)l * Dm * Dh, b1s + l * Dh);
        gemm_mlp<2><<<dim3(Bsz / 128, Dm / 128), 256>>>(W2s + (size_t)l * Dh * Dm, b2s + l * Dm);
    }

    head_kernel<<<Bsz, 256>>>(g_f, beta_f, W_head, b_head, (float*)d_out);
}

// round 3
// speedup vs baseline: 2.5531x; 2.5531x over previous
#include <cuda_runtime.h>
#include <cstdint>

// ---------------- problem constants ----------------
static constexpr int Bsz = 16384;
static constexpr int Dm  = 256;
static constexpr int Dh  = 512;

static constexpr int SMEM_DYN = 64 * 1024 + 1024;  // 2 x (16KB A + 16KB B) + align slack

// ---------------- device scratch (static; no runtime alloc) ----------------
__device__ float g_h [Bsz * Dm];
__device__ float g_ln[Bsz * Dm];
__device__ float g_t [Bsz * Dh];
__device__ float g_Anum[32 * 256];
__device__ float g_c[256];
__device__ float g_W1p[8 * 8  * 512 * 32];   // [l][kb][n][32] swizzled, tf32-rounded
__device__ float g_W2p[8 * 16 * 256 * 32];
__device__ float g_Wfp[129 * 256 * 32];      // kb0 = folded numeric, kb1..128 = cat

// ---------------- PTX helpers ----------------
__device__ __forceinline__ uint32_t sm32(const void* p) {
    uint32_t a;
    asm("{ .reg .u64 t; cvta.to.shared.u64 t, %1; cvt.u32.u64 %0, t; }" : "=r"(a) : "l"(p));
    return a;
}
__device__ __forceinline__ void cpa16(uint32_t dst, const void* src) {
    asm volatile("cp.async.cg.shared.global [%0], [%1], 16;" :: "r"(dst), "l"(src));
}
#define CPA_COMMIT() asm volatile("cp.async.commit_group;" ::: "memory")
#define CPA_WAIT(n)  asm volatile("cp.async.wait_group %0;" :: "n"(n) : "memory")

__device__ __forceinline__ void ldm4(uint32_t (&r)[4], uint32_t addr) {
    asm volatile("ldmatrix.sync.aligned.m8n8.x4.shared.b16 {%0,%1,%2,%3}, [%4];"
                 : "=r"(r[0]), "=r"(r[1]), "=r"(r[2]), "=r"(r[3]) : "r"(addr));
}
__device__ __forceinline__ uint32_t to_tf32(uint32_t v) {
    uint32_t o;
    asm("cvt.rna.tf32.f32 %0, %1;" : "=r"(o) : "f"(__uint_as_float(v)));
    return o;
}
__device__ __forceinline__ void mma_tf32(float (&d)[4], const uint32_t (&a)[4],
                                         uint32_t b0, uint32_t b1) {
    asm volatile("mma.sync.aligned.m16n8k8.row.col.f32.tf32.tf32.f32 "
                 "{%0,%1,%2,%3}, {%4,%5,%6,%7}, {%8,%9}, {%0,%1,%2,%3};"
                 : "+f"(d[0]), "+f"(d[1]), "+f"(d[2]), "+f"(d[3])
                 : "r"(a[0]), "r"(a[1]), "r"(a[2]), "r"(a[3]), "r"(b0), "r"(b1));
}

// ---------------- prep kernels ----------------
__global__ void prep_anum(const float* __restrict__ w_num, const float* __restrict__ W_first) {
    int f = blockIdx.x, j = threadIdx.x;
    const float* Wf = W_first + (size_t)f * 256 * 256 + j;
    const float* wn = w_num + f * 256;
    float acc = 0.f;
    for (int d = 0; d < 256; d++) acc = fmaf(wn[d], Wf[(size_t)d * 256], acc);
    g_Anum[f * 256 + j] = acc;
}
__global__ void prep_c(const float* __restrict__ b_num, const float* __restrict__ W_first,
                       const float* __restrict__ b_first) {
    int j = threadIdx.x;
    float acc = b_first[j];
    for (int k = 0; k < 8192; k++) acc = fmaf(b_num[k], W_first[(size_t)k * 256 + j], acc);
    g_c[j] = acc;
}
// pack K-major weight (Ktot x N row-major) -> [kb][n][32] swizzled + tf32-rounded
__global__ void pack_w(const float* __restrict__ src, float* __restrict__ dst, int Ktot, int N) {
    int total = (Ktot / 32) * N * 32;
    for (int i = blockIdx.x * blockDim.x + threadIdx.x; i < total; i += gridDim.x * blockDim.x) {
        int j  = i & 31;
        int n  = (i >> 5) % N;
        int kb = i / (N * 32);
        int k  = (((j >> 2) ^ (n & 7)) << 2) | (j & 3);
        float v = src[(size_t)(kb * 32 + k) * N + n];
        uint32_t t;
        asm("cvt.rna.tf32.f32 %0, %1;" : "=r"(t) : "f"(v));
        dst[i] = __uint_as_float(t);
    }
}

// ---------------- tensor-core GEMM via mma.sync tf32 ----------------
// MODE 0: first layer (A gathered from x_num / cat_embed), C = g_h
// MODE 1: g_t = relu(g_ln @ W1 + b1)
// MODE 2: g_h += g_t @ W2 + b2
template <int MODE, int K, int NOUT>
__global__ __launch_bounds__(256) void gemm_mma(
    const float* __restrict__ A, const float* __restrict__ Bp,
    float* __restrict__ C, const float* __restrict__ bias,
    const float* __restrict__ xnum, const int* __restrict__ xidx,
    const float* __restrict__ cemb)
{
    constexpr int NC = (MODE == 0) ? 129 : K / 32;
    extern __shared__ float dsm[];
    uint32_t raw  = sm32(dsm);
    uint32_t base = (raw + 1023u) & ~1023u;   // 128B+ aligned for swizzle pattern
    float* smf    = dsm + ((base - raw) >> 2);

    int tid = threadIdx.x, wid = tid >> 5, lane = tid & 31;
    int bm = blockIdx.x * 128, bn = blockIdx.y * 128;
    int r = tid >> 1, half = tid & 1, m = bm + r;

    // per-buffer layout: A = 4096 floats (128 rows x 32), B = 4096 floats (128 n x 32)
    auto issue = [&](int c, int b) {
        const float* asrc;
        if constexpr (MODE == 0) {
            if (c == 0) asrc = xnum + (size_t)m * 32 + half * 16;
            else {
                int cc = c - 1, f = cc >> 3, d0 = (cc & 7) << 5;
                asrc = cemb + (size_t)xidx[m * 16 + f] * 256 + d0 + half * 16;
            }
        } else {
            asrc = A + (size_t)m * K + c * 32 + half * 16;
        }
        uint32_t Ad = base + (uint32_t)b * 32768u + (uint32_t)r * 128u;
#pragma unroll
        for (int i = 0; i < 4; i++) {
            int g = half * 4 + i;
            cpa16(Ad + (uint32_t)((g ^ (r & 7)) * 16), asrc + i * 4);
        }
        const float* bsrc = Bp + ((size_t)c * NOUT + bn) * 32 + tid * 4;
        uint32_t Bd = base + (uint32_t)b * 32768u + 16384u + (uint32_t)tid * 16u;
#pragma unroll
        for (int i = 0; i < 4; i++) cpa16(Bd + i * 4096u, bsrc + i * 1024);
        CPA_COMMIT();
    };

    float acc[16][4];
#pragma unroll
    for (int t = 0; t < 16; t++)
#pragma unroll
        for (int q = 0; q < 4; q++) acc[t][q] = 0.f;

    int warp_m = wid & 3, warp_n = wid >> 2;
    int lr = lane & 7, lh = (lane >> 3) & 1, lg = lane >> 4;

    issue(0, 0);
    if (NC > 1) issue(1, 1);

    for (int c = 0; c < NC; c++) {
        if (c + 1 < NC) CPA_WAIT(1); else CPA_WAIT(0);
        __syncthreads();

        uint32_t Ab = base + (uint32_t)(c & 1) * 32768u;
        uint32_t Bb = Ab + 16384u;
#pragma unroll
        for (int s = 0; s < 4; s++) {
            uint32_t af[2][4];
#pragma unroll
            for (int i = 0; i < 2; i++) {
                int R = warp_m * 32 + i * 16 + lr + lh * 8;
                int g = s * 2 + lg;
                ldm4(af[i], Ab + (uint32_t)(R * 128 + ((g ^ (R & 7)) * 16)));
#pragma unroll
                for (int q = 0; q < 4; q++) af[i][q] = to_tf32(af[i][q]);
            }
            uint32_t bf[8][2];
#pragma unroll
            for (int p = 0; p < 4; p++) {
                int n = warp_n * 64 + p * 16 + lr + lh * 8;
                int g = s * 2 + lg;
                uint32_t t4[4];
                ldm4(t4, Bb + (uint32_t)(n * 128 + ((g ^ (n & 7)) * 16)));
                bf[2 * p][0] = t4[0]; bf[2 * p + 1][0] = t4[1];
                bf[2 * p][1] = t4[2]; bf[2 * p + 1][1] = t4[3];
            }
#pragma unroll
            for (int i = 0; i < 2; i++)
#pragma unroll
                for (int j = 0; j < 8; j++)
                    mma_tf32(acc[i * 8 + j], af[i], bf[j][0], bf[j][1]);
        }
        __syncthreads();
        if (c + 2 < NC) issue(c + 2, c & 1);
    }

    // ---- epilogue: bias / relu / residual, fp32 register accumulators ----
#pragma unroll
    for (int i = 0; i < 2; i++) {
#pragma unroll
        for (int j = 0; j < 8; j++) {
            int row0 = bm + warp_m * 32 + i * 16 + (lane >> 2);
            int col  = bn + warp_n * 64 + j * 8 + (lane & 3) * 2;
            float b0 = bias[col], b1 = bias[col + 1];
            float v0 = acc[i * 8 + j][0] + b0;
            float v1 = acc[i * 8 + j][1] + b1;
            float v2 = acc[i * 8 + j][2] + b0;
            float v3 = acc[i * 8 + j][3] + b1;
            if constexpr (MODE == 1) {
                v0 = fmaxf(v0, 0.f); v1 = fmaxf(v1, 0.f);
                v2 = fmaxf(v2, 0.f); v3 = fmaxf(v3, 0.f);
            }
            float* p0 = C + (size_t)row0 * NOUT + col;
            float* p1 = C + (size_t)(row0 + 8) * NOUT + col;
            if constexpr (MODE == 2) {
                float2 r0 = *(const float2*)p0;
                float2 r1 = *(const float2*)p1;
                v0 += r0.x; v1 += r0.y; v2 += r1.x; v3 += r1.y;
            }
            *(float2*)p0 = make_float2(v0, v1);
            *(float2*)p1 = make_float2(v2, v3);
        }
    }
}

// ---------------- warp-per-row layernorm ----------------
__global__ void ln_fast(const float* __restrict__ gam, const float* __restrict__ bet) {
    int w = threadIdx.x >> 5, lane = threadIdx.x & 31;
    int row = blockIdx.x * 8 + w;
    const float4* x = (const float4*)(g_h + (size_t)row * 256);
    float4 a = x[lane], b = x[lane + 32];
    float s = a.x + a.y + a.z + a.w + b.x + b.y + b.z + b.w;
    float q = a.x * a.x + a.y * a.y + a.z * a.z + a.w * a.w
            + b.x * b.x + b.y * b.y + b.z * b.z + b.w * b.w;
#pragma unroll
    for (int o = 16; o; o >>= 1) {
        s += __shfl_xor_sync(0xffffffffu, s, o);
        q += __shfl_xor_sync(0xffffffffu, q, o);
    }
    float mu = s * (1.f / 256.f);
    float rs = rsqrtf(q * (1.f / 256.f) - mu * mu + 1e-5f);
    float4 g0 = ((const float4*)gam)[lane], g1 = ((const float4*)gam)[lane + 32];
    float4 e0 = ((const float4*)bet)[lane], e1 = ((const float4*)bet)[lane + 32];
    float4 y0, y1;
    y0.x = (a.x - mu) * rs * g0.x + e0.x;  y0.y = (a.y - mu) * rs * g0.y + e0.y;
    y0.z = (a.z - mu) * rs * g0.z + e0.z;  y0.w = (a.w - mu) * rs * g0.w + e0.w;
    y1.x = (b.x - mu) * rs * g1.x + e1.x;  y1.y = (b.y - mu) * rs * g1.y + e1.y;
    y1.z = (b.z - mu) * rs * g1.z + e1.z;  y1.w = (b.w - mu) * rs * g1.w + e1.w;
    float4* out = (float4*)(g_ln + (size_t)row * 256);
    out[lane] = y0; out[lane + 32] = y1;
}

// ---------------- warp-per-row final LN + head ----------------
__global__ void head_fast(const float* __restrict__ gam, const float* __restrict__ bet,
                          const float* __restrict__ Wh, const float* __restrict__ bh,
                          float* __restrict__ out) {
    int w = threadIdx.x >> 5, lane = threadIdx.x & 31;
    int row = blockIdx.x * 8 + w;
    const float4* x = (const float4*)(g_h + (size_t)row * 256);
    float4 a = x[lane], b = x[lane + 32];
    float s = a.x + a.y + a.z + a.w + b.x + b.y + b.z + b.w;
    float q = a.x * a.x + a.y * a.y + a.z * a.z + a.w * a.w
            + b.x * b.x + b.y * b.y + b.z * b.z + b.w * b.w;
#pragma unroll
    for (int o = 16; o; o >>= 1) {
        s += __shfl_xor_sync(0xffffffffu, s, o);
        q += __shfl_xor_sync(0xffffffffu, q, o);
    }
    float mu = s * (1.f / 256.f);
    float rs = rsqrtf(q * (1.f / 256.f) - mu * mu + 1e-5f);
    float4 g0 = ((const float4*)gam)[lane], g1 = ((const float4*)gam)[lane + 32];
    float4 e0 = ((const float4*)bet)[lane], e1 = ((const float4*)bet)[lane + 32];
    float y[8];
    y[0] = (a.x - mu) * rs * g0.x + e0.x;  y[1] = (a.y - mu) * rs * g0.y + e0.y;
    y[2] = (a.z - mu) * rs * g0.z + e0.z;  y[3] = (a.w - mu) * rs * g0.w + e0.w;
    y[4] = (b.x - mu) * rs * g1.x + e1.x;  y[5] = (b.y - mu) * rs * g1.y + e1.y;
    y[6] = (b.z - mu) * rs * g1.z + e1.z;  y[7] = (b.w - mu) * rs * g1.w + e1.w;
    const float4* W4 = (const float4*)Wh;
    float4 wA = W4[lane * 2], wB = W4[lane * 2 + 1];
    float4 wC = W4[64 + lane * 2], wD = W4[64 + lane * 2 + 1];
    float s0 = y[0] * wA.x + y[1] * wA.z + y[2] * wB.x + y[3] * wB.z
             + y[4] * wC.x + y[5] * wC.z + y[6] * wD.x + y[7] * wD.z;
    float s1 = y[0] * wA.y + y[1] * wA.w + y[2] * wB.y + y[3] * wB.w
             + y[4] * wC.y + y[5] * wC.w + y[6] * wD.y + y[7] * wD.w;
#pragma unroll
    for (int o = 16; o; o >>= 1) {
        s0 += __shfl_xor_sync(0xffffffffu, s0, o);
        s1 += __shfl_xor_sync(0xffffffffu, s1, o);
    }
    if (lane == 0) {
        out[row * 2 + 0] = s0 + bh[0];
        out[row * 2 + 1] = s1 + bh[1];
    }
}

// ---------------- launch ----------------
extern "C" void kernel_launch(void* const* d_in, const int* in_sizes, int n_in,
                              void* d_out, int out_size) {
    const float* x_num   = (const float*)d_in[0];
    const int*   xidx    = (const int*)  d_in[1];
    const float* w_num   = (const float*)d_in[2];
    const float* b_num   = (const float*)d_in[3];
    const float* cat_emb = (const float*)d_in[4];
    const float* W_first = (const float*)d_in[5];
    const float* b_first = (const float*)d_in[6];
    const float* ln_g    = (const float*)d_in[7];
    const float* ln_b    = (const float*)d_in[8];
    const float* W1s     = (const float*)d_in[9];
    const float* b1s     = (const float*)d_in[10];
    const float* W2s     = (const float*)d_in[11];
    const float* b2s     = (const float*)d_in[12];
    const float* g_f     = (const float*)d_in[13];
    const float* beta_f  = (const float*)d_in[14];
    const float* W_head  = (const float*)d_in[15];
    const float* b_head  = (const float*)d_in[16];

    cudaFuncSetAttribute(gemm_mma<0, 4128, 256>, cudaFuncAttributeMaxDynamicSharedMemorySize, SMEM_DYN);
    cudaFuncSetAttribute(gemm_mma<1, 256,  512>, cudaFuncAttributeMaxDynamicSharedMemorySize, SMEM_DYN);
    cudaFuncSetAttribute(gemm_mma<2, 512,  256>, cudaFuncAttributeMaxDynamicSharedMemorySize, SMEM_DYN);

    float* g_Anum_p; cudaGetSymbolAddress((void**)&g_Anum_p, g_Anum);
    float* g_W1p_p;  cudaGetSymbolAddress((void**)&g_W1p_p,  g_W1p);
    float* g_W2p_p;  cudaGetSymbolAddress((void**)&g_W2p_p,  g_W2p);
    float* g_Wfp_p;  cudaGetSymbolAddress((void**)&g_Wfp_p,  g_Wfp);
    float* g_c_p;    cudaGetSymbolAddress((void**)&g_c_p,    g_c);
    float* g_h_p;    cudaGetSymbolAddress((void**)&g_h_p,    g_h);
    float* g_ln_p;   cudaGetSymbolAddress((void**)&g_ln_p,   g_ln);
    float* g_t_p;    cudaGetSymbolAddress((void**)&g_t_p,    g_t);

    prep_anum<<<32, 256>>>(w_num, W_first);
    prep_c<<<1, 256>>>(b_num, W_first, b_first);
    pack_w<<<2048, 256>>>(W1s, g_W1p_p, 8 * 256, 512);
    pack_w<<<2048, 256>>>(W2s, g_W2p_p, 8 * 512, 256);
    pack_w<<<64,   256>>>(g_Anum_p, g_Wfp_p, 32, 256);
    pack_w<<<2048, 256>>>(W_first + (size_t)8192 * 256, g_Wfp_p + 8192, 4096, 256);

    gemm_mma<0, 4128, 256><<<dim3(128, 2), 256, SMEM_DYN>>>(
        nullptr, g_Wfp_p, g_h_p, g_c_p, x_num, xidx, cat_emb);

    for (int l = 0; l < 8; l++) {
        ln_fast<<<2048, 256>>>(ln_g + l * 256, ln_b + l * 256);
        gemm_mma<1, 256, 512><<<dim3(128, 4), 256, SMEM_DYN>>>(
            g_ln_p, g_W1p_p + (size_t)l * 8 * 512 * 32, g_t_p, b1s + l * 512,
            nullptr, nullptr, nullptr);
        gemm_mma<2, 512, 256><<<dim3(128, 2), 256, SMEM_DYN>>>(
            g_t_p, g_W2p_p + (size_t)l * 16 * 256 * 32, g_h_p, b2s + l * 256,
            nullptr, nullptr, nullptr);
    }

    head_fast<<<2048, 256>>>(g_f, beta_f, W_head, b_head, (float*)d_out);
}

// round 4
// speedup vs baseline: 2.8743x; 1.1258x over previous
#include <cuda_runtime.h>
#include <cstdint>

// ---------------- problem constants ----------------
static constexpr int Bsz = 16384;
static constexpr int Dm  = 256;
static constexpr int Dh  = 512;

static constexpr int SMEM_WIDE = 96 * 1024 + 1024;   // 2 x (16KB A + 32KB B) + slack
static constexpr int SMEM_MLP1 = 64 * 1024 + 1024;   // 2 x (16KB A + 16KB B) + slack

// ---------------- device scratch (static; no runtime alloc) ----------------
__device__ float g_h [Bsz * Dm];
__device__ float g_ln[Bsz * Dm];
__device__ float g_t [Bsz * Dh];
__device__ float g_Anum[32 * 256];
__device__ float g_c[256];
__device__ float g_W1p[8 * 8  * 512 * 32];   // [l][kb][n][32] swizzled, tf32-rounded
__device__ float g_W2p[8 * 16 * 256 * 32];
__device__ float g_Wfp[129 * 256 * 32];      // kb0 = folded numeric, kb1..128 = cat

// ---------------- PTX helpers ----------------
__device__ __forceinline__ uint32_t sm32(const void* p) {
    uint32_t a;
    asm("{ .reg .u64 t; cvta.to.shared.u64 t, %1; cvt.u32.u64 %0, t; }" : "=r"(a) : "l"(p));
    return a;
}
__device__ __forceinline__ void cpa16(uint32_t dst, const void* src) {
    asm volatile("cp.async.cg.shared.global [%0], [%1], 16;" :: "r"(dst), "l"(src));
}
#define CPA_COMMIT() asm volatile("cp.async.commit_group;" ::: "memory")
#define CPA_WAIT(n)  asm volatile("cp.async.wait_group %0;" :: "n"(n) : "memory")

__device__ __forceinline__ void ldm4(uint32_t (&r)[4], uint32_t addr) {
    asm volatile("ldmatrix.sync.aligned.m8n8.x4.shared.b16 {%0,%1,%2,%3}, [%4];"
                 : "=r"(r[0]), "=r"(r[1]), "=r"(r[2]), "=r"(r[3]) : "r"(addr));
}
__device__ __forceinline__ uint32_t to_tf32(uint32_t v) {
    uint32_t o;
    asm("cvt.rna.tf32.f32 %0, %1;" : "=r"(o) : "f"(__uint_as_float(v)));
    return o;
}
__device__ __forceinline__ float round_tf32(float v) {
    uint32_t o;
    asm("cvt.rna.tf32.f32 %0, %1;" : "=r"(o) : "f"(v));
    return __uint_as_float(o);
}
__device__ __forceinline__ void mma_tf32(float (&d)[4], const uint32_t (&a)[4],
                                         uint32_t b0, uint32_t b1) {
    asm volatile("mma.sync.aligned.m16n8k8.row.col.f32.tf32.tf32.f32 "
                 "{%0,%1,%2,%3}, {%4,%5,%6,%7}, {%8,%9}, {%0,%1,%2,%3};"
                 : "+f"(d[0]), "+f"(d[1]), "+f"(d[2]), "+f"(d[3])
                 : "r"(a[0]), "r"(a[1]), "r"(a[2]), "r"(a[3]), "r"(b0), "r"(b1));
}

// ---------------- prep kernels ----------------
__global__ void prep_anum(const float* __restrict__ w_num, const float* __restrict__ W_first) {
    int f = blockIdx.x, j = threadIdx.x;
    const float* Wf = W_first + (size_t)f * 256 * 256 + j;
    const float* wn = w_num + f * 256;
    float acc = 0.f;
    for (int d = 0; d < 256; d++) acc = fmaf(wn[d], Wf[(size_t)d * 256], acc);
    g_Anum[f * 256 + j] = acc;
}
__global__ void prep_c(const float* __restrict__ b_num, const float* __restrict__ W_first,
                       const float* __restrict__ b_first) {
    int j = threadIdx.x;
    float acc = b_first[j];
    for (int k = 0; k < 8192; k++) acc = fmaf(b_num[k], W_first[(size_t)k * 256 + j], acc);
    g_c[j] = acc;
}
// pack K-major weight (Ktot x N row-major) -> [kb][n][32] swizzled + tf32-rounded
__global__ void pack_w(const float* __restrict__ src, float* __restrict__ dst, int Ktot, int N) {
    int total = (Ktot / 32) * N * 32;
    for (int i = blockIdx.x * blockDim.x + threadIdx.x; i < total; i += gridDim.x * blockDim.x) {
        int j  = i & 31;
        int n  = (i >> 5) % N;
        int kb = i / (N * 32);
        int k  = (((j >> 2) ^ (n & 7)) << 2) | (j & 3);
        dst[i] = round_tf32(src[(size_t)(kb * 32 + k) * N + n]);
    }
}

// =====================================================================
// WIDE GEMM: tile 128 x 256, 512 threads (16 warps, 4x4), fused LN epilogue
// MODE 0: C(pre-LN) = gathered_A @ Wf + c          -> g_h, LN -> g_ln
// MODE 2: C(pre-LN) = g_h + (g_t @ W2 + b2)        -> g_h, LN -> g_ln
// LAST=1: g_ln written full fp32 (head consumes); else tf32-rounded.
// =====================================================================
template <int MODE, int LAST>
__global__ __launch_bounds__(512, 1) void gemm_wide(
    const float* __restrict__ Bp, const float* __restrict__ bias,
    const float* __restrict__ gam, const float* __restrict__ bet,
    const float* __restrict__ xnum, const int* __restrict__ xidx,
    const float* __restrict__ cemb)
{
    constexpr int NC = (MODE == 0) ? 129 : 16;   // MODE2: K=512 -> 16 chunks
    extern __shared__ float dsm[];
    __shared__ float red_s[128 * 4], red_q[128 * 4];
    uint32_t raw  = sm32(dsm);
    uint32_t base = (raw + 1023u) & ~1023u;

    int tid = threadIdx.x, wid = tid >> 5, lane = tid & 31;
    int bm = blockIdx.x * 128;
    int warp_m = wid & 3, warp_n = wid >> 2;
    int lr = lane & 7, lh = (lane >> 3) & 1, lg = lane >> 4;

    int ar = tid >> 2, aq = tid & 3;          // A loader: 4 threads per row
    int m  = bm + ar;

    auto issue = [&](int c, int b) {
        const float* arow;
        if constexpr (MODE == 0) {
            if (c == 0) arow = xnum + (size_t)m * 32;
            else {
                int cc = c - 1, f = cc >> 3, d0 = (cc & 7) << 5;
                arow = cemb + (size_t)xidx[m * 16 + f] * 256 + d0;
            }
        } else {
            arow = g_t + (size_t)m * Dh + c * 32;
        }
        uint32_t Ad = base + (uint32_t)b * 49152u + (uint32_t)ar * 128u;
#pragma unroll
        for (int i = 0; i < 2; i++) {
            int g = aq + i * 4;
            cpa16(Ad + (uint32_t)((g ^ (ar & 7)) * 16), arow + g * 4);
        }
        const float4* bsrc = (const float4*)(Bp + (size_t)c * 256 * 32) + tid;
        uint32_t Bd = base + (uint32_t)b * 49152u + 16384u + (uint32_t)tid * 16u;
#pragma unroll
        for (int i = 0; i < 4; i++) cpa16(Bd + i * 8192u, bsrc + i * 512);
        CPA_COMMIT();
    };

    float acc[16][4];
#pragma unroll
    for (int t = 0; t < 16; t++)
#pragma unroll
        for (int q = 0; q < 4; q++) acc[t][q] = 0.f;

    issue(0, 0);
    issue(1, 1);

    for (int c = 0; c < NC; c++) {
        if (c + 1 < NC) CPA_WAIT(1); else CPA_WAIT(0);
        __syncthreads();
        uint32_t Ab = base + (uint32_t)(c & 1) * 49152u;
        uint32_t Bb = Ab + 16384u;
#pragma unroll
        for (int s = 0; s < 4; s++) {
            uint32_t af[2][4];
#pragma unroll
            for (int i = 0; i < 2; i++) {
                int R = warp_m * 32 + i * 16 + lr + lh * 8;
                int g = s * 2 + lg;
                ldm4(af[i], Ab + (uint32_t)(R * 128 + ((g ^ (R & 7)) * 16)));
                if constexpr (MODE == 0) {
#pragma unroll
                    for (int q = 0; q < 4; q++) af[i][q] = to_tf32(af[i][q]);
                }
            }
            uint32_t bf[8][2];
#pragma unroll
            for (int p = 0; p < 4; p++) {
                int n = warp_n * 64 + p * 16 + lr + lh * 8;
                int g = s * 2 + lg;
                uint32_t t4[4];
                ldm4(t4, Bb + (uint32_t)(n * 128 + ((g ^ (n & 7)) * 16)));
                bf[2 * p][0] = t4[0]; bf[2 * p + 1][0] = t4[1];
                bf[2 * p][1] = t4[2]; bf[2 * p + 1][1] = t4[3];
            }
#pragma unroll
            for (int i = 0; i < 2; i++)
#pragma unroll
                for (int j = 0; j < 8; j++)
                    mma_tf32(acc[i * 8 + j], af[i], bf[j][0], bf[j][1]);
        }
        __syncthreads();
        if (c + 2 < NC) issue(c + 2, c & 1);
    }

    // ---- fused epilogue: bias (+residual), write g_h, row LN, write g_ln ----
    float v[16][4];                      // post-bias(+res) values
    float ps[2] = {0.f, 0.f}, pq[2] = {0.f, 0.f};  // per-row-half partials (i=0: rows r0/r0+8 share? no)
    // rows handled by this thread: R(i,h) = warp_m*32 + i*16 + h*8 + (lane>>2), i in {0,1}, h in {0,1}
    float rs_[4] = {0.f, 0.f, 0.f, 0.f}, rq_[4] = {0.f, 0.f, 0.f, 0.f};
#pragma unroll
    for (int i = 0; i < 2; i++) {
#pragma unroll
        for (int j = 0; j < 8; j++) {
            int row0 = bm + warp_m * 32 + i * 16 + (lane >> 2);
            int col  = warp_n * 64 + j * 8 + (lane & 3) * 2;
            float b0 = bias[col], b1 = bias[col + 1];
            float v0 = acc[i * 8 + j][0] + b0;
            float v1 = acc[i * 8 + j][1] + b1;
            float v2 = acc[i * 8 + j][2] + b0;
            float v3 = acc[i * 8 + j][3] + b1;
            if constexpr (MODE == 2) {
                float2 r0 = *(const float2*)(g_h + (size_t)row0 * Dm + col);
                float2 r1 = *(const float2*)(g_h + (size_t)(row0 + 8) * Dm + col);
                v0 += r0.x; v1 += r0.y; v2 += r1.x; v3 += r1.y;
            }
            v[i * 8 + j][0] = v0; v[i * 8 + j][1] = v1;
            v[i * 8 + j][2] = v2; v[i * 8 + j][3] = v3;
            rs_[i * 2 + 0] += v0 + v1;            rq_[i * 2 + 0] += v0 * v0 + v1 * v1;
            rs_[i * 2 + 1] += v2 + v3;            rq_[i * 2 + 1] += v2 * v2 + v3 * v3;
            // write pre-LN h
            *(float2*)(g_h + (size_t)row0 * Dm + col)       = make_float2(v0, v1);
            *(float2*)(g_h + (size_t)(row0 + 8) * Dm + col) = make_float2(v2, v3);
        }
    }
    // reduce across the 4 lanes (lane&3) sharing each row
#pragma unroll
    for (int t = 0; t < 4; t++) {
#pragma unroll
        for (int o = 1; o <= 2; o <<= 1) {
            rs_[t] += __shfl_xor_sync(0xffffffffu, rs_[t], o);
            rq_[t] += __shfl_xor_sync(0xffffffffu, rq_[t], o);
        }
    }
    if ((lane & 3) == 0) {
#pragma unroll
        for (int i = 0; i < 2; i++)
#pragma unroll
            for (int h = 0; h < 2; h++) {
                int rloc = warp_m * 32 + i * 16 + h * 8 + (lane >> 2);
                red_s[rloc * 4 + warp_n] = rs_[i * 2 + h];
                red_q[rloc * 4 + warp_n] = rq_[i * 2 + h];
            }
    }
    __syncthreads();
#pragma unroll
    for (int i = 0; i < 2; i++) {
#pragma unroll
        for (int h = 0; h < 2; h++) {
            int rloc = warp_m * 32 + i * 16 + h * 8 + (lane >> 2);
            float s = red_s[rloc * 4 + 0] + red_s[rloc * 4 + 1]
                    + red_s[rloc * 4 + 2] + red_s[rloc * 4 + 3];
            float q = red_q[rloc * 4 + 0] + red_q[rloc * 4 + 1]
                    + red_q[rloc * 4 + 2] + red_q[rloc * 4 + 3];
            float mu = s * (1.f / 256.f);
            float rinv = rsqrtf(q * (1.f / 256.f) - mu * mu + 1e-5f);
            int grow = bm + rloc;
#pragma unroll
            for (int j = 0; j < 8; j++) {
                int col = warp_n * 64 + j * 8 + (lane & 3) * 2;
                float g0 = gam[col], g1 = gam[col + 1];
                float e0 = bet[col], e1 = bet[col + 1];
                float y0 = (v[i * 8 + j][h * 2 + 0] - mu) * rinv * g0 + e0;
                float y1 = (v[i * 8 + j][h * 2 + 1] - mu) * rinv * g1 + e1;
                if constexpr (!LAST) { y0 = round_tf32(y0); y1 = round_tf32(y1); }
                *(float2*)(g_ln + (size_t)grow * Dm + col) = make_float2(y0, y1);
            }
        }
    }
}

// =====================================================================
// MLP1 GEMM: tile 128 x 128, 256 threads. g_t = tf32(relu(g_ln @ W1 + b1))
// A (g_ln) is pre-rounded -> no cvt in mainloop.
// =====================================================================
__global__ __launch_bounds__(256) void gemm_mlp1(
    const float* __restrict__ Bp, const float* __restrict__ bias)
{
    constexpr int K = 256, NOUT = 512, NC = K / 32;
    extern __shared__ float dsm[];
    uint32_t raw  = sm32(dsm);
    uint32_t base = (raw + 1023u) & ~1023u;

    int tid = threadIdx.x, wid = tid >> 5, lane = tid & 31;
    int bm = blockIdx.x * 128, bn = blockIdx.y * 128;
    int r = tid >> 1, half = tid & 1, m = bm + r;

    auto issue = [&](int c, int b) {
        const float* asrc = g_ln + (size_t)m * K + c * 32 + half * 16;
        uint32_t Ad = base + (uint32_t)b * 32768u + (uint32_t)r * 128u;
#pragma unroll
        for (int i = 0; i < 4; i++) {
            int g = half * 4 + i;
            cpa16(Ad + (uint32_t)((g ^ (r & 7)) * 16), asrc + i * 4);
        }
        const float* bsrc = Bp + ((size_t)c * NOUT + bn) * 32 + tid * 4;
        uint32_t Bd = base + (uint32_t)b * 32768u + 16384u + (uint32_t)tid * 16u;
#pragma unroll
        for (int i = 0; i < 4; i++) cpa16(Bd + i * 4096u, bsrc + i * 1024);
        CPA_COMMIT();
    };

    float acc[16][4];
#pragma unroll
    for (int t = 0; t < 16; t++)
#pragma unroll
        for (int q = 0; q < 4; q++) acc[t][q] = 0.f;

    int warp_m = wid & 3, warp_n = wid >> 2;
    int lr = lane & 7, lh = (lane >> 3) & 1, lg = lane >> 4;

    issue(0, 0);
    issue(1, 1);

    for (int c = 0; c < NC; c++) {
        if (c + 1 < NC) CPA_WAIT(1); else CPA_WAIT(0);
        __syncthreads();
        uint32_t Ab = base + (uint32_t)(c & 1) * 32768u;
        uint32_t Bb = Ab + 16384u;
#pragma unroll
        for (int s = 0; s < 4; s++) {
            uint32_t af[2][4];
#pragma unroll
            for (int i = 0; i < 2; i++) {
                int R = warp_m * 32 + i * 16 + lr + lh * 8;
                int g = s * 2 + lg;
                ldm4(af[i], Ab + (uint32_t)(R * 128 + ((g ^ (R & 7)) * 16)));
            }
            uint32_t bf[8][2];
#pragma unroll
            for (int p = 0; p < 4; p++) {
                int n = warp_n * 64 + p * 16 + lr + lh * 8;
                int g = s * 2 + lg;
                uint32_t t4[4];
                ldm4(t4, Bb + (uint32_t)(n * 128 + ((g ^ (n & 7)) * 16)));
                bf[2 * p][0] = t4[0]; bf[2 * p + 1][0] = t4[1];
                bf[2 * p][1] = t4[2]; bf[2 * p + 1][1] = t4[3];
            }
#pragma unroll
            for (int i = 0; i < 2; i++)
#pragma unroll
                for (int j = 0; j < 8; j++)
                    mma_tf32(acc[i * 8 + j], af[i], bf[j][0], bf[j][1]);
        }
        __syncthreads();
        if (c + 2 < NC) issue(c + 2, c & 1);
    }

#pragma unroll
    for (int i = 0; i < 2; i++) {
#pragma unroll
        for (int j = 0; j < 8; j++) {
            int row0 = bm + warp_m * 32 + i * 16 + (lane >> 2);
            int col  = bn + warp_n * 64 + j * 8 + (lane & 3) * 2;
            float b0 = bias[col], b1 = bias[col + 1];
            float v0 = round_tf32(fmaxf(acc[i * 8 + j][0] + b0, 0.f));
            float v1 = round_tf32(fmaxf(acc[i * 8 + j][1] + b1, 0.f));
            float v2 = round_tf32(fmaxf(acc[i * 8 + j][2] + b0, 0.f));
            float v3 = round_tf32(fmaxf(acc[i * 8 + j][3] + b1, 0.f));
            *(float2*)(g_t + (size_t)row0 * Dh + col)       = make_float2(v0, v1);
            *(float2*)(g_t + (size_t)(row0 + 8) * Dh + col) = make_float2(v2, v3);
        }
    }
}

// ---------------- head: matvec over final LN output (already in g_ln) ----------
__global__ void head_fast(const float* __restrict__ Wh, const float* __restrict__ bh,
                          float* __restrict__ out) {
    int w = threadIdx.x >> 5, lane = threadIdx.x & 31;
    int row = blockIdx.x * 8 + w;
    const float4* x = (const float4*)(g_ln + (size_t)row * 256);
    float4 a = x[lane], b = x[lane + 32];
    float y[8] = {a.x, a.y, a.z, a.w, b.x, b.y, b.z, b.w};
    const float4* W4 = (const float4*)Wh;
    float4 wA = W4[lane * 2], wB = W4[lane * 2 + 1];
    float4 wC = W4[64 + lane * 2], wD = W4[64 + lane * 2 + 1];
    float s0 = y[0] * wA.x + y[1] * wA.z + y[2] * wB.x + y[3] * wB.z
             + y[4] * wC.x + y[5] * wC.z + y[6] * wD.x + y[7] * wD.z;
    float s1 = y[0] * wA.y + y[1] * wA.w + y[2] * wB.y + y[3] * wB.w
             + y[4] * wC.y + y[5] * wC.w + y[6] * wD.y + y[7] * wD.w;
#pragma unroll
    for (int o = 16; o; o >>= 1) {
        s0 += __shfl_xor_sync(0xffffffffu, s0, o);
        s1 += __shfl_xor_sync(0xffffffffu, s1, o);
    }
    if (lane == 0) {
        out[row * 2 + 0] = s0 + bh[0];
        out[row * 2 + 1] = s1 + bh[1];
    }
}

// ---------------- launch ----------------
extern "C" void kernel_launch(void* const* d_in, const int* in_sizes, int n_in,
                              void* d_out, int out_size) {
    const float* x_num   = (const float*)d_in[0];
    const int*   xidx    = (const int*)  d_in[1];
    const float* w_num   = (const float*)d_in[2];
    const float* b_num   = (const float*)d_in[3];
    const float* cat_emb = (const float*)d_in[4];
    const float* W_first = (const float*)d_in[5];
    const float* b_first = (const float*)d_in[6];
    const float* ln_g    = (const float*)d_in[7];
    const float* ln_b    = (const float*)d_in[8];
    const float* W1s     = (const float*)d_in[9];
    const float* b1s     = (const float*)d_in[10];
    const float* W2s     = (const float*)d_in[11];
    const float* b2s     = (const float*)d_in[12];
    const float* g_f     = (const float*)d_in[13];
    const float* beta_f  = (const float*)d_in[14];
    const float* W_head  = (const float*)d_in[15];
    const float* b_head  = (const float*)d_in[16];

    cudaFuncSetAttribute(gemm_wide<0, 0>, cudaFuncAttributeMaxDynamicSharedMemorySize, SMEM_WIDE);
    cudaFuncSetAttribute(gemm_wide<2, 0>, cudaFuncAttributeMaxDynamicSharedMemorySize, SMEM_WIDE);
    cudaFuncSetAttribute(gemm_wide<2, 1>, cudaFuncAttributeMaxDynamicSharedMemorySize, SMEM_WIDE);
    cudaFuncSetAttribute(gemm_mlp1,       cudaFuncAttributeMaxDynamicSharedMemorySize, SMEM_MLP1);

    float* g_Anum_p; cudaGetSymbolAddress((void**)&g_Anum_p, g_Anum);
    float* g_W1p_p;  cudaGetSymbolAddress((void**)&g_W1p_p,  g_W1p);
    float* g_W2p_p;  cudaGetSymbolAddress((void**)&g_W2p_p,  g_W2p);
    float* g_Wfp_p;  cudaGetSymbolAddress((void**)&g_Wfp_p,  g_Wfp);
    float* g_c_p;    cudaGetSymbolAddress((void**)&g_c_p,    g_c);

    prep_anum<<<32, 256>>>(w_num, W_first);
    prep_c<<<1, 256>>>(b_num, W_first, b_first);
    pack_w<<<2048, 256>>>(W1s, g_W1p_p, 8 * 256, 512);
    pack_w<<<2048, 256>>>(W2s, g_W2p_p, 8 * 512, 256);
    pack_w<<<64,   256>>>(g_Anum_p, g_Wfp_p, 32, 256);
    pack_w<<<2048, 256>>>(W_first + (size_t)8192 * 256, g_Wfp_p + 8192, 4096, 256);

    // first layer + LN(layer 0) fused
    gemm_wide<0, 0><<<128, 512, SMEM_WIDE>>>(
        g_Wfp_p, g_c_p, ln_g, ln_b, x_num, xidx, cat_emb);

    for (int l = 0; l < 8; l++) {
        gemm_mlp1<<<dim3(128, 4), 256, SMEM_MLP1>>>(
            g_W1p_p + (size_t)l * 8 * 512 * 32, b1s + l * 512);
        const float* gam = (l < 7) ? (ln_g + (l + 1) * 256) : g_f;
        const float* bet = (l < 7) ? (ln_b + (l + 1) * 256) : beta_f;
        if (l < 7)
            gemm_wide<2, 0><<<128, 512, SMEM_WIDE>>>(
                g_W2p_p + (size_t)l * 16 * 256 * 32, b2s + l * 256, gam, bet,
                nullptr, nullptr, nullptr);
        else
            gemm_wide<2, 1><<<128, 512, SMEM_WIDE>>>(
                g_W2p_p + (size_t)l * 16 * 256 * 32, b2s + l * 256, gam, bet,
                nullptr, nullptr, nullptr);
    }

    head_fast<<<2048, 256>>>(W_head, b_head, (float*)d_out);
}

// round 5
// speedup vs baseline: 3.8921x; 1.3541x over previous
#include <cuda_runtime.h>
#include <cstdint>

// ---------------- problem constants ----------------
static constexpr int Bsz = 16384;
static constexpr int Dm  = 256;
static constexpr int Dh  = 512;

static constexpr int SMEM_W128 = 98304 + 1024;   // 2x(16KB A + 32KB B)
static constexpr int SMEM_W64  = 81920 + 1024;   // 2x( 8KB A + 32KB B)
static constexpr int SMEM_MLP1 = 64 * 1024 + 1024;

// ---------------- device scratch ----------------
__device__ float g_h [Bsz * Dm];
__device__ float g_ln[Bsz * Dm];
__device__ float g_t [Bsz * Dh];
__device__ float g_Anum[32 * 256];
__device__ float g_c[256];
__device__ float g_cpart[32 * 256];
__device__ float g_W1p[8 * 8  * 512 * 32];
__device__ float g_W2p[8 * 16 * 256 * 32];
__device__ float g_Wfp[129 * 256 * 32];

// ---------------- PTX helpers ----------------
__device__ __forceinline__ uint32_t sm32(const void* p) {
    uint32_t a;
    asm("{ .reg .u64 t; cvta.to.shared.u64 t, %1; cvt.u32.u64 %0, t; }" : "=r"(a) : "l"(p));
    return a;
}
__device__ __forceinline__ void cpa16(uint32_t dst, const void* src) {
    asm volatile("cp.async.cg.shared.global [%0], [%1], 16;" :: "r"(dst), "l"(src));
}
#define CPA_COMMIT() asm volatile("cp.async.commit_group;" ::: "memory")
#define CPA_WAIT(n)  asm volatile("cp.async.wait_group %0;" :: "n"(n) : "memory")

__device__ __forceinline__ void ldm4(uint32_t (&r)[4], uint32_t addr) {
    asm volatile("ldmatrix.sync.aligned.m8n8.x4.shared.b16 {%0,%1,%2,%3}, [%4];"
                 : "=r"(r[0]), "=r"(r[1]), "=r"(r[2]), "=r"(r[3]) : "r"(addr));
}
__device__ __forceinline__ uint32_t to_tf32(uint32_t v) {
    uint32_t o;
    asm("cvt.rna.tf32.f32 %0, %1;" : "=r"(o) : "f"(__uint_as_float(v)));
    return o;
}
__device__ __forceinline__ float round_tf32(float v) {
    uint32_t o;
    asm("cvt.rna.tf32.f32 %0, %1;" : "=r"(o) : "f"(v));
    return __uint_as_float(o);
}
__device__ __forceinline__ void mma_tf32(float (&d)[4], const uint32_t (&a)[4],
                                         uint32_t b0, uint32_t b1) {
    asm volatile("mma.sync.aligned.m16n8k8.row.col.f32.tf32.tf32.f32 "
                 "{%0,%1,%2,%3}, {%4,%5,%6,%7}, {%8,%9}, {%0,%1,%2,%3};"
                 : "+f"(d[0]), "+f"(d[1]), "+f"(d[2]), "+f"(d[3])
                 : "r"(a[0]), "r"(a[1]), "r"(a[2]), "r"(a[3]), "r"(b0), "r"(b1));
}

// ---------------- prep kernels ----------------
__global__ void prep_anum(const float* __restrict__ w_num, const float* __restrict__ W_first) {
    int f = blockIdx.x, j = threadIdx.x;
    const float* Wf = W_first + (size_t)f * 256 * 256 + j;
    const float* wn = w_num + f * 256;
    float acc = 0.f;
    for (int d = 0; d < 256; d++) acc = fmaf(wn[d], Wf[(size_t)d * 256], acc);
    g_Anum[f * 256 + j] = acc;
}
__global__ void prep_c1(const float* __restrict__ b_num, const float* __restrict__ W_first) {
    int b = blockIdx.x, j = threadIdx.x;
    float acc = 0.f;
    const float* W = W_first + (size_t)b * 256 * 256 + j;
    const float* bn = b_num + b * 256;
    for (int k = 0; k < 256; k++) acc = fmaf(bn[k], W[(size_t)k * 256], acc);
    g_cpart[b * 256 + j] = acc;
}
__global__ void prep_c2(const float* __restrict__ b_first) {
    int j = threadIdx.x;
    float acc = b_first[j];
    for (int b = 0; b < 32; b++) acc += g_cpart[b * 256 + j];
    g_c[j] = acc;
}
__global__ void pack_w(const float* __restrict__ src, float* __restrict__ dst, int Ktot, int N) {
    int total = (Ktot / 32) * N * 32;
    for (int i = blockIdx.x * blockDim.x + threadIdx.x; i < total; i += gridDim.x * blockDim.x) {
        int j  = i & 31;
        int n  = (i >> 5) % N;
        int kb = i / (N * 32);
        int k  = (((j >> 2) ^ (n & 7)) << 2) | (j & 3);
        dst[i] = round_tf32(src[(size_t)(kb * 32 + k) * N + n]);
    }
}

// =====================================================================
// WIDE GEMM: tile TM x 256, NTHR = 4*TM threads, fused LN epilogue.
// MODE 0: C(pre-LN) = gathered_A @ Wf + c       -> g_h, LN -> g_ln
// MODE 2: C(pre-LN) = g_h + (g_t @ W2 + b2)     -> g_h, LN -> g_ln
// LAST=1 (MODE 2): skip g_h/g_ln stores, compute head matvec -> out.
// =====================================================================
template <int MODE, int LAST, int TM, int NTHR>
__global__ __launch_bounds__(NTHR, (TM == 64) ? 2 : 1) void gemm_wide(
    const float* __restrict__ Bp, const float* __restrict__ bias,
    const float* __restrict__ gam, const float* __restrict__ bet,
    const float* __restrict__ xnum, const int* __restrict__ xidx,
    const float* __restrict__ cemb,
    const float* __restrict__ Wh, const float* __restrict__ bh,
    float* __restrict__ out)
{
    constexpr int NC  = (MODE == 0) ? 129 : 16;
    constexpr int WM  = TM / 32;                // warp_m count
    constexpr int ASZ = TM * 128;               // A buffer bytes
    extern __shared__ float dsm[];
    __shared__ float red_s[TM * 4], red_q[TM * 4];
    uint32_t raw  = sm32(dsm);
    uint32_t base = (raw + 1023u) & ~1023u;

    int tid = threadIdx.x, wid = tid >> 5, lane = tid & 31;
    int bm = blockIdx.x * TM;
    int warp_m = wid % WM, warp_n = wid / WM;
    int lr = lane & 7, lh = (lane >> 3) & 1, lg = lane >> 4;

    int ar = tid >> 2, aq = tid & 3;            // 4 threads per A row
    int m  = bm + ar;

    auto issue = [&](int c, int b) {
        const float* arow;
        if constexpr (MODE == 0) {
            if (c == 0) arow = xnum + (size_t)m * 32;
            else {
                int cc = c - 1, f = cc >> 3, d0 = (cc & 7) << 5;
                arow = cemb + (size_t)xidx[m * 16 + f] * 256 + d0;
            }
        } else {
            arow = g_t + (size_t)m * Dh + c * 32;
        }
        uint32_t Ad = base + (uint32_t)b * ASZ + (uint32_t)ar * 128u;
#pragma unroll
        for (int i = 0; i < 2; i++) {
            int g = aq + i * 4;
            cpa16(Ad + (uint32_t)((g ^ (ar & 7)) * 16), arow + g * 4);
        }
        const float4* bsrc = (const float4*)(Bp + (size_t)c * 256 * 32) + tid;
        uint32_t Bd = base + 2u * ASZ + (uint32_t)b * 32768u + (uint32_t)tid * 16u;
#pragma unroll
        for (int i = 0; i < 2048 / NTHR; i++)
            cpa16(Bd + (uint32_t)i * (NTHR * 16u), bsrc + i * NTHR);
        CPA_COMMIT();
    };

    float acc[16][4];
#pragma unroll
    for (int t = 0; t < 16; t++)
#pragma unroll
        for (int q = 0; q < 4; q++) acc[t][q] = 0.f;

    issue(0, 0);
    issue(1, 1);

    for (int c = 0; c < NC; c++) {
        if (c + 1 < NC) CPA_WAIT(1); else CPA_WAIT(0);
        __syncthreads();
        uint32_t Ab = base + (uint32_t)(c & 1) * ASZ;
        uint32_t Bb = base + 2u * ASZ + (uint32_t)(c & 1) * 32768u;
#pragma unroll
        for (int s = 0; s < 4; s++) {
            uint32_t af[2][4];
#pragma unroll
            for (int i = 0; i < 2; i++) {
                int R = warp_m * 32 + i * 16 + lr + lh * 8;
                int g = s * 2 + lg;
                ldm4(af[i], Ab + (uint32_t)(R * 128 + ((g ^ (R & 7)) * 16)));
                if constexpr (MODE == 0) {
#pragma unroll
                    for (int q = 0; q < 4; q++) af[i][q] = to_tf32(af[i][q]);
                }
            }
            uint32_t bf[8][2];
#pragma unroll
            for (int p = 0; p < 4; p++) {
                int n = warp_n * 64 + p * 16 + lr + lh * 8;
                int g = s * 2 + lg;
                uint32_t t4[4];
                ldm4(t4, Bb + (uint32_t)(n * 128 + ((g ^ (n & 7)) * 16)));
                bf[2 * p][0] = t4[0]; bf[2 * p + 1][0] = t4[1];
                bf[2 * p][1] = t4[2]; bf[2 * p + 1][1] = t4[3];
            }
#pragma unroll
            for (int i = 0; i < 2; i++)
#pragma unroll
                for (int j = 0; j < 8; j++)
                    mma_tf32(acc[i * 8 + j], af[i], bf[j][0], bf[j][1]);
        }
        __syncthreads();
        if (c + 2 < NC) issue(c + 2, c & 1);
    }

    // ---- fused epilogue ----
    float v[16][4];
    float rs_[4] = {0.f, 0.f, 0.f, 0.f}, rq_[4] = {0.f, 0.f, 0.f, 0.f};
#pragma unroll
    for (int i = 0; i < 2; i++) {
#pragma unroll
        for (int j = 0; j < 8; j++) {
            int row0 = bm + warp_m * 32 + i * 16 + (lane >> 2);
            int col  = warp_n * 64 + j * 8 + (lane & 3) * 2;
            float b0 = bias[col], b1 = bias[col + 1];
            float v0 = acc[i * 8 + j][0] + b0;
            float v1 = acc[i * 8 + j][1] + b1;
            float v2 = acc[i * 8 + j][2] + b0;
            float v3 = acc[i * 8 + j][3] + b1;
            if constexpr (MODE == 2) {
                float2 r0 = *(const float2*)(g_h + (size_t)row0 * Dm + col);
                float2 r1 = *(const float2*)(g_h + (size_t)(row0 + 8) * Dm + col);
                v0 += r0.x; v1 += r0.y; v2 += r1.x; v3 += r1.y;
            }
            v[i * 8 + j][0] = v0; v[i * 8 + j][1] = v1;
            v[i * 8 + j][2] = v2; v[i * 8 + j][3] = v3;
            rs_[i * 2 + 0] += v0 + v1;  rq_[i * 2 + 0] += v0 * v0 + v1 * v1;
            rs_[i * 2 + 1] += v2 + v3;  rq_[i * 2 + 1] += v2 * v2 + v3 * v3;
            if constexpr (!LAST) {
                *(float2*)(g_h + (size_t)row0 * Dm + col)       = make_float2(v0, v1);
                *(float2*)(g_h + (size_t)(row0 + 8) * Dm + col) = make_float2(v2, v3);
            }
        }
    }
#pragma unroll
    for (int t = 0; t < 4; t++) {
#pragma unroll
        for (int o = 1; o <= 2; o <<= 1) {
            rs_[t] += __shfl_xor_sync(0xffffffffu, rs_[t], o);
            rq_[t] += __shfl_xor_sync(0xffffffffu, rq_[t], o);
        }
    }
    if ((lane & 3) == 0) {
#pragma unroll
        for (int i = 0; i < 2; i++)
#pragma unroll
            for (int h = 0; h < 2; h++) {
                int rloc = warp_m * 32 + i * 16 + h * 8 + (lane >> 2);
                red_s[rloc * 4 + warp_n] = rs_[i * 2 + h];
                red_q[rloc * 4 + warp_n] = rq_[i * 2 + h];
            }
    }
    __syncthreads();

    float hd0[4] = {0.f, 0.f, 0.f, 0.f}, hd1[4] = {0.f, 0.f, 0.f, 0.f};
#pragma unroll
    for (int i = 0; i < 2; i++) {
#pragma unroll
        for (int h = 0; h < 2; h++) {
            int rloc = warp_m * 32 + i * 16 + h * 8 + (lane >> 2);
            float s = red_s[rloc * 4 + 0] + red_s[rloc * 4 + 1]
                    + red_s[rloc * 4 + 2] + red_s[rloc * 4 + 3];
            float q = red_q[rloc * 4 + 0] + red_q[rloc * 4 + 1]
                    + red_q[rloc * 4 + 2] + red_q[rloc * 4 + 3];
            float mu = s * (1.f / 256.f);
            float rinv = rsqrtf(q * (1.f / 256.f) - mu * mu + 1e-5f);
            int grow = bm + rloc;
#pragma unroll
            for (int j = 0; j < 8; j++) {
                int col = warp_n * 64 + j * 8 + (lane & 3) * 2;
                float g0 = gam[col], g1 = gam[col + 1];
                float e0 = bet[col], e1 = bet[col + 1];
                float y0 = (v[i * 8 + j][h * 2 + 0] - mu) * rinv * g0 + e0;
                float y1 = (v[i * 8 + j][h * 2 + 1] - mu) * rinv * g1 + e1;
                if constexpr (LAST) {
                    hd0[i * 2 + h] += y0 * Wh[col * 2 + 0] + y1 * Wh[col * 2 + 2];
                    hd1[i * 2 + h] += y0 * Wh[col * 2 + 1] + y1 * Wh[col * 2 + 3];
                } else {
                    y0 = round_tf32(y0); y1 = round_tf32(y1);
                    *(float2*)(g_ln + (size_t)grow * Dm + col) = make_float2(y0, y1);
                }
            }
        }
    }
    if constexpr (LAST) {
#pragma unroll
        for (int t = 0; t < 4; t++) {
#pragma unroll
            for (int o = 1; o <= 2; o <<= 1) {
                hd0[t] += __shfl_xor_sync(0xffffffffu, hd0[t], o);
                hd1[t] += __shfl_xor_sync(0xffffffffu, hd1[t], o);
            }
        }
        __syncthreads();   // red arrays free for reuse
        if ((lane & 3) == 0) {
#pragma unroll
            for (int i = 0; i < 2; i++)
#pragma unroll
                for (int h = 0; h < 2; h++) {
                    int rloc = warp_m * 32 + i * 16 + h * 8 + (lane >> 2);
                    red_s[rloc * 4 + warp_n] = hd0[i * 2 + h];
                    red_q[rloc * 4 + warp_n] = hd1[i * 2 + h];
                }
        }
        __syncthreads();
        if (tid < TM) {
            float s0 = red_s[tid * 4 + 0] + red_s[tid * 4 + 1]
                     + red_s[tid * 4 + 2] + red_s[tid * 4 + 3];
            float s1 = red_q[tid * 4 + 0] + red_q[tid * 4 + 1]
                     + red_q[tid * 4 + 2] + red_q[tid * 4 + 3];
            out[(bm + tid) * 2 + 0] = s0 + bh[0];
            out[(bm + tid) * 2 + 1] = s1 + bh[1];
        }
    }
}

// =====================================================================
// MLP1 GEMM: tile 128 x 128, 256 threads. g_t = tf32(relu(g_ln @ W1 + b1))
// =====================================================================
__global__ __launch_bounds__(256) void gemm_mlp1(
    const float* __restrict__ Bp, const float* __restrict__ bias)
{
    constexpr int K = 256, NOUT = 512, NC = K / 32;
    extern __shared__ float dsm[];
    uint32_t raw  = sm32(dsm);
    uint32_t base = (raw + 1023u) & ~1023u;

    int tid = threadIdx.x, wid = tid >> 5, lane = tid & 31;
    int bm = blockIdx.x * 128, bn = blockIdx.y * 128;
    int r = tid >> 1, half = tid & 1, m = bm + r;

    auto issue = [&](int c, int b) {
        const float* asrc = g_ln + (size_t)m * K + c * 32 + half * 16;
        uint32_t Ad = base + (uint32_t)b * 32768u + (uint32_t)r * 128u;
#pragma unroll
        for (int i = 0; i < 4; i++) {
            int g = half * 4 + i;
            cpa16(Ad + (uint32_t)((g ^ (r & 7)) * 16), asrc + i * 4);
        }
        const float* bsrc = Bp + ((size_t)c * NOUT + bn) * 32 + tid * 4;
        uint32_t Bd = base + (uint32_t)b * 32768u + 16384u + (uint32_t)tid * 16u;
#pragma unroll
        for (int i = 0; i < 4; i++) cpa16(Bd + i * 4096u, bsrc + i * 1024);
        CPA_COMMIT();
    };

    float acc[16][4];
#pragma unroll
    for (int t = 0; t < 16; t++)
#pragma unroll
        for (int q = 0; q < 4; q++) acc[t][q] = 0.f;

    int warp_m = wid & 3, warp_n = wid >> 2;
    int lr = lane & 7, lh = (lane >> 3) & 1, lg = lane >> 4;

    issue(0, 0);
    issue(1, 1);

    for (int c = 0; c < NC; c++) {
        if (c + 1 < NC) CPA_WAIT(1); else CPA_WAIT(0);
        __syncthreads();
        uint32_t Ab = base + (uint32_t)(c & 1) * 32768u;
        uint32_t Bb = Ab + 16384u;
#pragma unroll
        for (int s = 0; s < 4; s++) {
            uint32_t af[2][4];
#pragma unroll
            for (int i = 0; i < 2; i++) {
                int R = warp_m * 32 + i * 16 + lr + lh * 8;
                int g = s * 2 + lg;
                ldm4(af[i], Ab + (uint32_t)(R * 128 + ((g ^ (R & 7)) * 16)));
            }
            uint32_t bf[8][2];
#pragma unroll
            for (int p = 0; p < 4; p++) {
                int n = warp_n * 64 + p * 16 + lr + lh * 8;
                int g = s * 2 + lg;
                uint32_t t4[4];
                ldm4(t4, Bb + (uint32_t)(n * 128 + ((g ^ (n & 7)) * 16)));
                bf[2 * p][0] = t4[0]; bf[2 * p + 1][0] = t4[1];
                bf[2 * p][1] = t4[2]; bf[2 * p + 1][1] = t4[3];
            }
#pragma unroll
            for (int i = 0; i < 2; i++)
#pragma unroll
                for (int j = 0; j < 8; j++)
                    mma_tf32(acc[i * 8 + j], af[i], bf[j][0], bf[j][1]);
        }
        __syncthreads();
        if (c + 2 < NC) issue(c + 2, c & 1);
    }

#pragma unroll
    for (int i = 0; i < 2; i++) {
#pragma unroll
        for (int j = 0; j < 8; j++) {
            int row0 = bm + warp_m * 32 + i * 16 + (lane >> 2);
            int col  = bn + warp_n * 64 + j * 8 + (lane & 3) * 2;
            float b0 = bias[col], b1 = bias[col + 1];
            float v0 = round_tf32(fmaxf(acc[i * 8 + j][0] + b0, 0.f));
            float v1 = round_tf32(fmaxf(acc[i * 8 + j][1] + b1, 0.f));
            float v2 = round_tf32(fmaxf(acc[i * 8 + j][2] + b0, 0.f));
            float v3 = round_tf32(fmaxf(acc[i * 8 + j][3] + b1, 0.f));
            *(float2*)(g_t + (size_t)row0 * Dh + col)       = make_float2(v0, v1);
            *(float2*)(g_t + (size_t)(row0 + 8) * Dh + col) = make_float2(v2, v3);
        }
    }
}

// ---------------- launch ----------------
extern "C" void kernel_launch(void* const* d_in, const int* in_sizes, int n_in,
                              void* d_out, int out_size) {
    const float* x_num   = (const float*)d_in[0];
    const int*   xidx    = (const int*)  d_in[1];
    const float* w_num   = (const float*)d_in[2];
    const float* b_num   = (const float*)d_in[3];
    const float* cat_emb = (const float*)d_in[4];
    const float* W_first = (const float*)d_in[5];
    const float* b_first = (const float*)d_in[6];
    const float* ln_g    = (const float*)d_in[7];
    const float* ln_b    = (const float*)d_in[8];
    const float* W1s     = (const float*)d_in[9];
    const float* b1s     = (const float*)d_in[10];
    const float* W2s     = (const float*)d_in[11];
    const float* b2s     = (const float*)d_in[12];
    const float* g_f     = (const float*)d_in[13];
    const float* beta_f  = (const float*)d_in[14];
    const float* W_head  = (const float*)d_in[15];
    const float* b_head  = (const float*)d_in[16];

    cudaFuncSetAttribute(gemm_wide<0, 0, 128, 512>, cudaFuncAttributeMaxDynamicSharedMemorySize, SMEM_W128);
    cudaFuncSetAttribute(gemm_wide<2, 0, 64, 256>,  cudaFuncAttributeMaxDynamicSharedMemorySize, SMEM_W64);
    cudaFuncSetAttribute(gemm_wide<2, 1, 64, 256>,  cudaFuncAttributeMaxDynamicSharedMemorySize, SMEM_W64);
    cudaFuncSetAttribute(gemm_mlp1, cudaFuncAttributeMaxDynamicSharedMemorySize, SMEM_MLP1);

    float* g_Anum_p; cudaGetSymbolAddress((void**)&g_Anum_p, g_Anum);
    float* g_W1p_p;  cudaGetSymbolAddress((void**)&g_W1p_p,  g_W1p);
    float* g_W2p_p;  cudaGetSymbolAddress((void**)&g_W2p_p,  g_W2p);
    float* g_Wfp_p;  cudaGetSymbolAddress((void**)&g_Wfp_p,  g_Wfp);
    float* g_c_p;    cudaGetSymbolAddress((void**)&g_c_p,    g_c);

    prep_anum<<<32, 256>>>(w_num, W_first);
    prep_c1<<<32, 256>>>(b_num, W_first);
    prep_c2<<<1, 256>>>(b_first);
    pack_w<<<2048, 256>>>(W1s, g_W1p_p, 8 * 256, 512);
    pack_w<<<2048, 256>>>(W2s, g_W2p_p, 8 * 512, 256);
    pack_w<<<64,   256>>>(g_Anum_p, g_Wfp_p, 32, 256);
    pack_w<<<2048, 256>>>(W_first + (size_t)8192 * 256, g_Wfp_p + 8192, 4096, 256);

    // first layer + LN(layer 0) fused
    gemm_wide<0, 0, 128, 512><<<128, 512, SMEM_W128>>>(
        g_Wfp_p, g_c_p, ln_g, ln_b, x_num, xidx, cat_emb, nullptr, nullptr, nullptr);

    for (int l = 0; l < 8; l++) {
        gemm_mlp1<<<dim3(128, 4), 256, SMEM_MLP1>>>(
            g_W1p_p + (size_t)l * 8 * 512 * 32, b1s + l * 512);
        if (l < 7)
            gemm_wide<2, 0, 64, 256><<<256, 256, SMEM_W64>>>(
                g_W2p_p + (size_t)l * 16 * 256 * 32, b2s + l * 256,
                ln_g + (l + 1) * 256, ln_b + (l + 1) * 256,
                nullptr, nullptr, nullptr, nullptr, nullptr, nullptr);
        else
            gemm_wide<2, 1, 64, 256><<<256, 256, SMEM_W64>>>(
                g_W2p_p + (size_t)l * 16 * 256 * 32, b2s + l * 256,
                g_f, beta_f, nullptr, nullptr, nullptr,
                W_head, b_head, (float*)d_out);
    }
}

// round 6
// speedup vs baseline: 4.1928x; 1.0773x over previous
#include <cuda_runtime.h>
#include <cstdint>

// ---------------- problem constants ----------------
static constexpr int Bsz = 16384;
static constexpr int SMEM_DYN = 104 * 1024 + 1024;   // ln 64K + tchunk 8K + wbuf 32K (+align)

// ---------------- device scratch ----------------
__device__ float g_Anum[32 * 256];
__device__ float g_c[256];
__device__ float g_cpart[32 * 256];
__device__ float g_W1p[8 * 8  * 512 * 32];   // [l][kb][n(512)][32] swizzled tf32
__device__ float g_W2p[8 * 16 * 256 * 32];   // [l][kb][n(256)][32] swizzled tf32
__device__ float g_Wfp[129 * 256 * 32];      // first-layer packed (kb0 = folded numeric)

// ---------------- PTX helpers ----------------
__device__ __forceinline__ uint32_t sm32(const void* p) {
    uint32_t a;
    asm("{ .reg .u64 t; cvta.to.shared.u64 t, %1; cvt.u32.u64 %0, t; }" : "=r"(a) : "l"(p));
    return a;
}
__device__ __forceinline__ void cpa16(uint32_t dst, const void* src) {
    asm volatile("cp.async.cg.shared.global [%0], [%1], 16;" :: "r"(dst), "l"(src));
}
#define CPA_COMMIT() asm volatile("cp.async.commit_group;" ::: "memory")
#define CPA_WAIT(n)  asm volatile("cp.async.wait_group %0;" :: "n"(n) : "memory")

__device__ __forceinline__ void ldm4(uint32_t (&r)[4], uint32_t addr) {
    asm volatile("ldmatrix.sync.aligned.m8n8.x4.shared.b16 {%0,%1,%2,%3}, [%4];"
                 : "=r"(r[0]), "=r"(r[1]), "=r"(r[2]), "=r"(r[3]) : "r"(addr));
}
__device__ __forceinline__ uint32_t to_tf32(uint32_t v) {
    uint32_t o;
    asm("cvt.rna.tf32.f32 %0, %1;" : "=r"(o) : "f"(__uint_as_float(v)));
    return o;
}
__device__ __forceinline__ float round_tf32(float v) {
    uint32_t o;
    asm("cvt.rna.tf32.f32 %0, %1;" : "=r"(o) : "f"(v));
    return __uint_as_float(o);
}
__device__ __forceinline__ void mma_tf32(float (&d)[4], const uint32_t (&a)[4],
                                         uint32_t b0, uint32_t b1) {
    asm volatile("mma.sync.aligned.m16n8k8.row.col.f32.tf32.tf32.f32 "
                 "{%0,%1,%2,%3}, {%4,%5,%6,%7}, {%8,%9}, {%0,%1,%2,%3};"
                 : "+f"(d[0]), "+f"(d[1]), "+f"(d[2]), "+f"(d[3])
                 : "r"(a[0]), "r"(a[1]), "r"(a[2]), "r"(a[3]), "r"(b0), "r"(b1));
}
__device__ __forceinline__ void st2s(uint32_t addr, float x, float y) {
    asm volatile("st.shared.v2.f32 [%0], {%1, %2};" :: "r"(addr), "f"(x), "f"(y));
}

// ---------------- prep kernels ----------------
__global__ void prep_anum(const float* __restrict__ w_num, const float* __restrict__ W_first) {
    int f = blockIdx.x, j = threadIdx.x;
    const float* Wf = W_first + (size_t)f * 256 * 256 + j;
    const float* wn = w_num + f * 256;
    float acc = 0.f;
    for (int d = 0; d < 256; d++) acc = fmaf(wn[d], Wf[(size_t)d * 256], acc);
    g_Anum[f * 256 + j] = acc;
}
__global__ void prep_c1(const float* __restrict__ b_num, const float* __restrict__ W_first) {
    int b = blockIdx.x, j = threadIdx.x;
    float acc = 0.f;
    const float* W = W_first + (size_t)b * 256 * 256 + j;
    const float* bn = b_num + b * 256;
    for (int k = 0; k < 256; k++) acc = fmaf(bn[k], W[(size_t)k * 256], acc);
    g_cpart[b * 256 + j] = acc;
}
__global__ void prep_c2(const float* __restrict__ b_first) {
    int j = threadIdx.x;
    float acc = b_first[j];
    for (int b = 0; b < 32; b++) acc += g_cpart[b * 256 + j];
    g_c[j] = acc;
}
__global__ void pack_w(const float* __restrict__ src, float* __restrict__ dst, int Ktot, int N) {
    int total = (Ktot / 32) * N * 32;
    for (int i = blockIdx.x * blockDim.x + threadIdx.x; i < total; i += gridDim.x * blockDim.x) {
        int j  = i & 31;
        int n  = (i >> 5) % N;
        int kb = i / (N * 32);
        int k  = (((j >> 2) ^ (n & 7)) << 2) | (j & 3);
        dst[i] = round_tf32(src[(size_t)(kb * 32 + k) * N + n]);
    }
}

// =====================================================================
// Persistent fused network kernel. One CTA = 64 rows through everything.
// 256 threads, occ 2, grid 256 (single resident wave on 148 SMs).
// Residual stream h lives in registers (hreg == mma accumulators).
// =====================================================================
__global__ __launch_bounds__(256, 2) void fused_net(
    const float* __restrict__ xnum, const int* __restrict__ xidx,
    const float* __restrict__ cemb,
    const float* __restrict__ b1g, const float* __restrict__ b2g,
    const float* __restrict__ lng, const float* __restrict__ lnbet,
    const float* __restrict__ gf,  const float* __restrict__ betf,
    const float* __restrict__ Wh,  const float* __restrict__ bh,
    float* __restrict__ out)
{
    extern __shared__ float dsm[];
    __shared__ float red_s[64 * 4], red_q[64 * 4];
    uint32_t raw  = sm32(dsm);
    uint32_t base = (raw + 1023u) & ~1023u;
    const uint32_t LNB = base;            // 64 KB: ln tile, 8 chunks of (64r x 32k)
    const uint32_t TCH = base + 65536u;   //  8 KB: t chunk (64r x 32k)
    const uint32_t WB  = base + 73728u;   // 32 KB: weight staging

    int tid = threadIdx.x, wid = tid >> 5, lane = tid & 31;
    int bm = blockIdx.x * 64;
    int warp_m = wid & 1, warp_n = wid >> 1;   // GEMM2 / phase0: 2 x 4 (64 x 256)
    int wm1 = wid & 3,    wn1 = wid >> 2;      // GEMM1: 4 x 2 (64 x 32)
    int lr = lane & 7, lh = (lane >> 3) & 1, lg = lane >> 4;

    float hreg[16][4];
#pragma unroll
    for (int t = 0; t < 16; t++)
#pragma unroll
        for (int q = 0; q < 4; q++) hreg[t][q] = 0.f;

    // ================= Phase 0: first GEMM (gathered A, K=4128) ==========
    {
        int ar = tid >> 2, aq = tid & 3, m = bm + ar;
        auto issue = [&](int c, int b) {
            const float* arow;
            if (c == 0) arow = xnum + (size_t)m * 32;
            else {
                int cc = c - 1, f = cc >> 3, d0 = (cc & 7) << 5;
                arow = cemb + (size_t)xidx[m * 16 + f] * 256 + d0;
            }
            uint32_t Ad = base + (uint32_t)b * 8192u + (uint32_t)ar * 128u;
#pragma unroll
            for (int i = 0; i < 2; i++) {
                int g = aq + i * 4;
                cpa16(Ad + (uint32_t)((g ^ (ar & 7)) << 4), arow + g * 4);
            }
            const float4* bsrc = (const float4*)(g_Wfp + (size_t)c * 8192) + tid;
            uint32_t Bd = base + 16384u + (uint32_t)b * 32768u + (uint32_t)tid * 16u;
#pragma unroll
            for (int i = 0; i < 8; i++) cpa16(Bd + (uint32_t)i * 4096u, bsrc + i * 256);
            CPA_COMMIT();
        };
        issue(0, 0);
        issue(1, 1);
#pragma unroll 1
        for (int c = 0; c < 129; c++) {
            if (c + 1 < 129) CPA_WAIT(1); else CPA_WAIT(0);
            __syncthreads();
            uint32_t Ab = base + (uint32_t)(c & 1) * 8192u;
            uint32_t Bb = base + 16384u + (uint32_t)(c & 1) * 32768u;
#pragma unroll
            for (int s = 0; s < 4; s++) {
                uint32_t af[2][4];
#pragma unroll
                for (int i = 0; i < 2; i++) {
                    int R = warp_m * 32 + i * 16 + lr + lh * 8;
                    int g = s * 2 + lg;
                    ldm4(af[i], Ab + (uint32_t)(R * 128 + ((g ^ (R & 7)) << 4)));
#pragma unroll
                    for (int q = 0; q < 4; q++) af[i][q] = to_tf32(af[i][q]);
                }
                uint32_t bf[8][2];
#pragma unroll
                for (int p = 0; p < 4; p++) {
                    int n = warp_n * 64 + p * 16 + lr + lh * 8;
                    int g = s * 2 + lg;
                    uint32_t t4[4];
                    ldm4(t4, Bb + (uint32_t)(n * 128 + ((g ^ (n & 7)) << 4)));
                    bf[2 * p][0] = t4[0]; bf[2 * p + 1][0] = t4[1];
                    bf[2 * p][1] = t4[2]; bf[2 * p + 1][1] = t4[3];
                }
#pragma unroll
                for (int i = 0; i < 2; i++)
#pragma unroll
                    for (int j = 0; j < 8; j++)
                        mma_tf32(hreg[i * 8 + j], af[i], bf[j][0], bf[j][1]);
            }
            __syncthreads();
            if (c + 2 < 129) issue(c + 2, c & 1);
        }
        // folded bias
#pragma unroll
        for (int i = 0; i < 2; i++)
#pragma unroll
            for (int j = 0; j < 8; j++) {
                int col = warp_n * 64 + j * 8 + (lane & 3) * 2;
                float b0 = g_c[col], b1 = g_c[col + 1];
                hreg[i * 8 + j][0] += b0; hreg[i * 8 + j][1] += b1;
                hreg[i * 8 + j][2] += b0; hreg[i * 8 + j][3] += b1;
            }
    }

    // ---- LN from hreg -> ln smem (tf32-rounded) ----
    auto do_ln = [&](const float* gam, const float* bet) {
        float rs_[4] = {0.f, 0.f, 0.f, 0.f}, rq_[4] = {0.f, 0.f, 0.f, 0.f};
#pragma unroll
        for (int i = 0; i < 2; i++)
#pragma unroll
            for (int j = 0; j < 8; j++) {
                float v0 = hreg[i * 8 + j][0], v1 = hreg[i * 8 + j][1];
                float v2 = hreg[i * 8 + j][2], v3 = hreg[i * 8 + j][3];
                rs_[i * 2 + 0] += v0 + v1;  rq_[i * 2 + 0] += v0 * v0 + v1 * v1;
                rs_[i * 2 + 1] += v2 + v3;  rq_[i * 2 + 1] += v2 * v2 + v3 * v3;
            }
#pragma unroll
        for (int t = 0; t < 4; t++)
#pragma unroll
            for (int o = 1; o <= 2; o <<= 1) {
                rs_[t] += __shfl_xor_sync(0xffffffffu, rs_[t], o);
                rq_[t] += __shfl_xor_sync(0xffffffffu, rq_[t], o);
            }
        if ((lane & 3) == 0) {
#pragma unroll
            for (int i = 0; i < 2; i++)
#pragma unroll
                for (int h = 0; h < 2; h++) {
                    int rloc = warp_m * 32 + i * 16 + h * 8 + (lane >> 2);
                    red_s[rloc * 4 + warp_n] = rs_[i * 2 + h];
                    red_q[rloc * 4 + warp_n] = rq_[i * 2 + h];
                }
        }
        __syncthreads();
#pragma unroll
        for (int i = 0; i < 2; i++)
#pragma unroll
            for (int h = 0; h < 2; h++) {
                int rloc = warp_m * 32 + i * 16 + h * 8 + (lane >> 2);
                float s = red_s[rloc * 4 + 0] + red_s[rloc * 4 + 1]
                        + red_s[rloc * 4 + 2] + red_s[rloc * 4 + 3];
                float q = red_q[rloc * 4 + 0] + red_q[rloc * 4 + 1]
                        + red_q[rloc * 4 + 2] + red_q[rloc * 4 + 3];
                float mu = s * (1.f / 256.f);
                float rinv = rsqrtf(q * (1.f / 256.f) - mu * mu + 1e-5f);
#pragma unroll
                for (int j = 0; j < 8; j++) {
                    int col = warp_n * 64 + j * 8 + (lane & 3) * 2;
                    float y0 = round_tf32((hreg[i * 8 + j][h * 2 + 0] - mu) * rinv * gam[col]     + bet[col]);
                    float y1 = round_tf32((hreg[i * 8 + j][h * 2 + 1] - mu) * rinv * gam[col + 1] + bet[col + 1]);
                    int cc = col & 31, kb = col >> 5;
                    uint32_t addr = LNB + (uint32_t)(kb * 8192 + rloc * 128
                                   + (((cc >> 2) ^ (rloc & 7)) << 4) + (cc & 3) * 4);
                    st2s(addr, y0, y1);
                }
            }
        __syncthreads();
    };

    // ================= 8 residual layers =================
#pragma unroll 1
    for (int l = 0; l < 8; l++) {
        do_ln(lng + l * 256, lnbet + l * 256);
        const float* W1 = g_W1p + (size_t)l * 8 * 512 * 32;
        const float* W2 = g_W2p + (size_t)l * 16 * 256 * 32;
        const float* b1 = b1g + l * 512;
#pragma unroll 1
        for (int kc = 0; kc < 16; kc++) {
            // ---- load W1 slice (8 pieces of 4KB) into WB ----
#pragma unroll
            for (int i = 0; i < 8; i++)
                cpa16(WB + (uint32_t)(i * 4096 + tid * 16),
                      W1 + ((size_t)i * 512 + kc * 32) * 32 + tid * 4);
            CPA_COMMIT();
            CPA_WAIT(0);
            __syncthreads();
            // ---- GEMM1: tchunk(64x32) = ln(64x256) @ W1slice ----
            float a1[2][4] = {};
#pragma unroll
            for (int kb = 0; kb < 8; kb++) {
#pragma unroll
                for (int s = 0; s < 4; s++) {
                    int g = s * 2 + lg;
                    uint32_t af[4];
                    int R = wm1 * 16 + lr + lh * 8;
                    ldm4(af, LNB + (uint32_t)(kb * 8192 + R * 128 + ((g ^ (R & 7)) << 4)));
                    int n = wn1 * 16 + lr + lh * 8;
                    uint32_t t4[4];
                    ldm4(t4, WB + (uint32_t)(kb * 4096 + n * 128 + ((g ^ (n & 7)) << 4)));
                    mma_tf32(a1[0], af, t4[0], t4[2]);
                    mma_tf32(a1[1], af, t4[1], t4[3]);
                }
            }
            // ---- relu + bias + round -> tchunk smem ----
#pragma unroll
            for (int f = 0; f < 2; f++) {
                int row0 = wm1 * 16 + (lane >> 2);
                int colL = wn1 * 16 + f * 8 + (lane & 3) * 2;
                int gc = kc * 32 + colL;
                float bb0 = b1[gc], bb1 = b1[gc + 1];
                float t0 = round_tf32(fmaxf(a1[f][0] + bb0, 0.f));
                float t1 = round_tf32(fmaxf(a1[f][1] + bb1, 0.f));
                float t2 = round_tf32(fmaxf(a1[f][2] + bb0, 0.f));
                float t3 = round_tf32(fmaxf(a1[f][3] + bb1, 0.f));
                uint32_t sw = (uint32_t)((((colL >> 2) ^ (row0 & 7)) << 4) + (colL & 3) * 4);
                st2s(TCH + (uint32_t)(row0 * 128) + sw, t0, t1);
                st2s(TCH + (uint32_t)((row0 + 8) * 128) + sw, t2, t3);
            }
            __syncthreads();
            // ---- load W2 chunk (32KB) into WB ----
            {
                const float4* w2s = (const float4*)(W2 + (size_t)kc * 8192) + tid;
#pragma unroll
                for (int i = 0; i < 8; i++)
                    cpa16(WB + (uint32_t)(tid * 16 + i * 4096), w2s + i * 256);
            }
            CPA_COMMIT();
            CPA_WAIT(0);
            __syncthreads();
            // ---- GEMM2: hreg += tchunk(64x32) @ W2chunk(32x256) ----
#pragma unroll
            for (int s = 0; s < 4; s++) {
                int g = s * 2 + lg;
                uint32_t af[2][4];
#pragma unroll
                for (int i = 0; i < 2; i++) {
                    int R = warp_m * 32 + i * 16 + lr + lh * 8;
                    ldm4(af[i], TCH + (uint32_t)(R * 128 + ((g ^ (R & 7)) << 4)));
                }
                uint32_t bf[8][2];
#pragma unroll
                for (int p = 0; p < 4; p++) {
                    int n = warp_n * 64 + p * 16 + lr + lh * 8;
                    uint32_t t4[4];
                    ldm4(t4, WB + (uint32_t)(n * 128 + ((g ^ (n & 7)) << 4)));
                    bf[2 * p][0] = t4[0]; bf[2 * p + 1][0] = t4[1];
                    bf[2 * p][1] = t4[2]; bf[2 * p + 1][1] = t4[3];
                }
#pragma unroll
                for (int i = 0; i < 2; i++)
#pragma unroll
                    for (int j = 0; j < 8; j++)
                        mma_tf32(hreg[i * 8 + j], af[i], bf[j][0], bf[j][1]);
            }
            __syncthreads();
        }
        // ---- b2 bias ----
        const float* b2 = b2g + l * 256;
#pragma unroll
        for (int i = 0; i < 2; i++)
#pragma unroll
            for (int j = 0; j < 8; j++) {
                int col = warp_n * 64 + j * 8 + (lane & 3) * 2;
                float b0 = b2[col], b1v = b2[col + 1];
                hreg[i * 8 + j][0] += b0;  hreg[i * 8 + j][1] += b1v;
                hreg[i * 8 + j][2] += b0;  hreg[i * 8 + j][3] += b1v;
            }
    }

    // ================= final LN + head =================
    {
        float rs_[4] = {0.f, 0.f, 0.f, 0.f}, rq_[4] = {0.f, 0.f, 0.f, 0.f};
#pragma unroll
        for (int i = 0; i < 2; i++)
#pragma unroll
            for (int j = 0; j < 8; j++) {
                float v0 = hreg[i * 8 + j][0], v1 = hreg[i * 8 + j][1];
                float v2 = hreg[i * 8 + j][2], v3 = hreg[i * 8 + j][3];
                rs_[i * 2 + 0] += v0 + v1;  rq_[i * 2 + 0] += v0 * v0 + v1 * v1;
                rs_[i * 2 + 1] += v2 + v3;  rq_[i * 2 + 1] += v2 * v2 + v3 * v3;
            }
#pragma unroll
        for (int t = 0; t < 4; t++)
#pragma unroll
            for (int o = 1; o <= 2; o <<= 1) {
                rs_[t] += __shfl_xor_sync(0xffffffffu, rs_[t], o);
                rq_[t] += __shfl_xor_sync(0xffffffffu, rq_[t], o);
            }
        if ((lane & 3) == 0) {
#pragma unroll
            for (int i = 0; i < 2; i++)
#pragma unroll
                for (int h = 0; h < 2; h++) {
                    int rloc = warp_m * 32 + i * 16 + h * 8 + (lane >> 2);
                    red_s[rloc * 4 + warp_n] = rs_[i * 2 + h];
                    red_q[rloc * 4 + warp_n] = rq_[i * 2 + h];
                }
        }
        __syncthreads();
        float hd0[4] = {0.f, 0.f, 0.f, 0.f}, hd1[4] = {0.f, 0.f, 0.f, 0.f};
#pragma unroll
        for (int i = 0; i < 2; i++)
#pragma unroll
            for (int h = 0; h < 2; h++) {
                int rloc = warp_m * 32 + i * 16 + h * 8 + (lane >> 2);
                float s = red_s[rloc * 4 + 0] + red_s[rloc * 4 + 1]
                        + red_s[rloc * 4 + 2] + red_s[rloc * 4 + 3];
                float q = red_q[rloc * 4 + 0] + red_q[rloc * 4 + 1]
                        + red_q[rloc * 4 + 2] + red_q[rloc * 4 + 3];
                float mu = s * (1.f / 256.f);
                float rinv = rsqrtf(q * (1.f / 256.f) - mu * mu + 1e-5f);
#pragma unroll
                for (int j = 0; j < 8; j++) {
                    int col = warp_n * 64 + j * 8 + (lane & 3) * 2;
                    float y0 = (hreg[i * 8 + j][h * 2 + 0] - mu) * rinv * gf[col]     + betf[col];
                    float y1 = (hreg[i * 8 + j][h * 2 + 1] - mu) * rinv * gf[col + 1] + betf[col + 1];
                    hd0[i * 2 + h] += y0 * Wh[col * 2 + 0] + y1 * Wh[col * 2 + 2];
                    hd1[i * 2 + h] += y0 * Wh[col * 2 + 1] + y1 * Wh[col * 2 + 3];
                }
            }
#pragma unroll
        for (int t = 0; t < 4; t++)
#pragma unroll
            for (int o = 1; o <= 2; o <<= 1) {
                hd0[t] += __shfl_xor_sync(0xffffffffu, hd0[t], o);
                hd1[t] += __shfl_xor_sync(0xffffffffu, hd1[t], o);
            }
        __syncthreads();
        if ((lane & 3) == 0) {
#pragma unroll
            for (int i = 0; i < 2; i++)
#pragma unroll
                for (int h = 0; h < 2; h++) {
                    int rloc = warp_m * 32 + i * 16 + h * 8 + (lane >> 2);
                    red_s[rloc * 4 + warp_n] = hd0[i * 2 + h];
                    red_q[rloc * 4 + warp_n] = hd1[i * 2 + h];
                }
        }
        __syncthreads();
        if (tid < 64) {
            float s0 = red_s[tid * 4 + 0] + red_s[tid * 4 + 1]
                     + red_s[tid * 4 + 2] + red_s[tid * 4 + 3];
            float s1 = red_q[tid * 4 + 0] + red_q[tid * 4 + 1]
                     + red_q[tid * 4 + 2] + red_q[tid * 4 + 3];
            out[(bm + tid) * 2 + 0] = s0 + bh[0];
            out[(bm + tid) * 2 + 1] = s1 + bh[1];
        }
    }
}

// ---------------- launch ----------------
extern "C" void kernel_launch(void* const* d_in, const int* in_sizes, int n_in,
                              void* d_out, int out_size) {
    const float* x_num   = (const float*)d_in[0];
    const int*   xidx    = (const int*)  d_in[1];
    const float* w_num   = (const float*)d_in[2];
    const float* b_num   = (const float*)d_in[3];
    const float* cat_emb = (const float*)d_in[4];
    const float* W_first = (const float*)d_in[5];
    const float* b_first = (const float*)d_in[6];
    const float* ln_g    = (const float*)d_in[7];
    const float* ln_b    = (const float*)d_in[8];
    const float* W1s     = (const float*)d_in[9];
    const float* b1s     = (const float*)d_in[10];
    const float* W2s     = (const float*)d_in[11];
    const float* b2s     = (const float*)d_in[12];
    const float* g_f     = (const float*)d_in[13];
    const float* beta_f  = (const float*)d_in[14];
    const float* W_head  = (const float*)d_in[15];
    const float* b_head  = (const float*)d_in[16];

    cudaFuncSetAttribute(fused_net, cudaFuncAttributeMaxDynamicSharedMemorySize, SMEM_DYN);

    float* g_Anum_p; cudaGetSymbolAddress((void**)&g_Anum_p, g_Anum);
    float* g_W1p_p;  cudaGetSymbolAddress((void**)&g_W1p_p,  g_W1p);
    float* g_W2p_p;  cudaGetSymbolAddress((void**)&g_W2p_p,  g_W2p);
    float* g_Wfp_p;  cudaGetSymbolAddress((void**)&g_Wfp_p,  g_Wfp);

    prep_anum<<<32, 256>>>(w_num, W_first);
    prep_c1<<<32, 256>>>(b_num, W_first);
    prep_c2<<<1, 256>>>(b_first);
    pack_w<<<2048, 256>>>(W1s, g_W1p_p, 8 * 256, 512);
    pack_w<<<2048, 256>>>(W2s, g_W2p_p, 8 * 512, 256);
    pack_w<<<64,   256>>>(g_Anum_p, g_Wfp_p, 32, 256);
    pack_w<<<2048, 256>>>(W_first + (size_t)8192 * 256, g_Wfp_p + 8192, 4096, 256);

    fused_net<<<256, 256, SMEM_DYN>>>(
        x_num, xidx, cat_emb, b1s, b2s, ln_g, ln_b,
        g_f, beta_f, W_head, b_head, (float*)d_out);
}